// round 5
// baseline (speedup 1.0000x reference)
#include <cuda_runtime.h>
#include <math.h>

#define BB 32
#define SS 96
#define TN 96
#define EE 256
#define HH 512
#define H4 2048
#define H2 1024
#define VV 32000

// ---------------- static scratch (no allocations) ----------------
__device__ float d_xsrc[BB*SS*EE];
__device__ float d_ytrg[BB*TN*EE];
__device__ float d_xpf[BB*SS*H4];
__device__ float d_xpb[BB*SS*H4];
__device__ float d_x1[BB*SS*H2];
__device__ float d_x2[BB*SS*H2];
__device__ float d_enc[BB*SS*HH];
__device__ float d_y1[BB*TN*HH];
__device__ float d_y2[BB*TN*HH];
__device__ float d_comb[BB*TN*H2];
__device__ float d_ecT0[BB*H2];   // encoder layer0 cell state, concat(f,b)
__device__ float d_ecT1[BB*H2];
__device__ float d_ehT0[BB*H2];   // encoder layer0 final h, concat(f,b)
__device__ float d_ehT1[BB*H2];
__device__ float d_dh0[BB*HH];    // decoder initial h per layer
__device__ float d_dh1[BB*HH];
__device__ float d_dc0[BB*HH];    // decoder cell state (init = c0 proj)
__device__ float d_dc1[BB*HH];
__device__ float d_zeros[BB*HH];

// ---------------- helpers ----------------
__global__ void zero_kernel(float* __restrict__ p, int n) {
    int i = blockIdx.x * blockDim.x + threadIdx.x;
    if (i < n) p[i] = 0.f;
}

__global__ void embed_kernel(float* __restrict__ out, const float* __restrict__ emb,
                             const int* __restrict__ seq, int n) {
    int i = blockIdx.x * blockDim.x + threadIdx.x;
    if (i < n) {
        int tok = seq[i >> 8];                      // E = 256
        out[i] = emb[(size_t)tok * EE + (i & 255)];
    }
}

// ---------------- SGEMM: C[M,N] = A[M,K] @ W[N,K]^T + bias[N] ----------------
// 128x128 tile, 256 threads, 8x8 per-thread register tile, K staged in 16-chunks.
// Requires: K % 16 == 0, N % 128 == 0 (true for all uses). M guarded.
__global__ __launch_bounds__(256) void sgemm_bias_nt(
    const float* __restrict__ A, const float* __restrict__ W,
    const float* __restrict__ bias, float* __restrict__ C,
    int M, int N, int K)
{
    __shared__ float As[16][132];
    __shared__ float Ws[16][132];
    const int bm = blockIdx.y * 128;
    const int bn = blockIdx.x * 128;
    const int tid = threadIdx.x;
    const int trow = (tid >> 4) * 8;
    const int tcol = (tid & 15) * 8;

    float acc[8][8];
#pragma unroll
    for (int i = 0; i < 8; i++)
#pragma unroll
        for (int j = 0; j < 8; j++) acc[i][j] = 0.f;

    for (int k0 = 0; k0 < K; k0 += 16) {
#pragma unroll
        for (int i = 0; i < 2; i++) {
            int q = tid + i * 256;          // 0..511
            int r = q >> 2;                 // 0..127
            int c = (q & 3) * 4;            // 0,4,8,12
            float4 v = make_float4(0.f, 0.f, 0.f, 0.f);
            if (bm + r < M) v = *(const float4*)(A + (size_t)(bm + r) * K + k0 + c);
            As[c + 0][r] = v.x; As[c + 1][r] = v.y; As[c + 2][r] = v.z; As[c + 3][r] = v.w;
            float4 u = *(const float4*)(W + (size_t)(bn + r) * K + k0 + c);
            Ws[c + 0][r] = u.x; Ws[c + 1][r] = u.y; Ws[c + 2][r] = u.z; Ws[c + 3][r] = u.w;
        }
        __syncthreads();
#pragma unroll
        for (int kk = 0; kk < 16; kk++) {
            float4 a0 = *(const float4*)&As[kk][trow];
            float4 a1 = *(const float4*)&As[kk][trow + 4];
            float4 b0 = *(const float4*)&Ws[kk][tcol];
            float4 b1 = *(const float4*)&Ws[kk][tcol + 4];
            float av[8] = {a0.x, a0.y, a0.z, a0.w, a1.x, a1.y, a1.z, a1.w};
            float bv[8] = {b0.x, b0.y, b0.z, b0.w, b1.x, b1.y, b1.z, b1.w};
#pragma unroll
            for (int i = 0; i < 8; i++)
#pragma unroll
                for (int j = 0; j < 8; j++) acc[i][j] += av[i] * bv[j];
        }
        __syncthreads();
    }

    float bb[8];
#pragma unroll
    for (int j = 0; j < 8; j++) bb[j] = bias[bn + tcol + j];
#pragma unroll
    for (int i = 0; i < 8; i++) {
        int r = bm + trow + i;
        if (r < M) {
            float* cp = C + (size_t)r * N + bn + tcol;
#pragma unroll
            for (int j = 0; j < 8; j += 4) {
                float4 v;
                v.x = acc[i][j + 0] + bb[j + 0];
                v.y = acc[i][j + 1] + bb[j + 1];
                v.z = acc[i][j + 2] + bb[j + 2];
                v.w = acc[i][j + 3] + bb[j + 3];
                *(float4*)(cp + j) = v;
            }
        }
    }
}

// ---------------- one LSTM timestep ----------------
// Grid: (64, ndir) blocks x 128 threads. Per block: 8 units (j0..j0+7) x all 4
// gates x 32 batches. Computes g = xp[t] + h_prev @ U^T, then the cell update,
// writes h into the output sequence hs and c in place.
// xp layout: [B][96][2048].  U: [2048][512].  h0: [B][512] (stride 512).
// hs: base pointer (dir offset pre-added), element (b,t,j) at (b*96+t)*ostr + j.
// cbuf: element (b,j) at b*cstr + j (dir offset pre-added).
__global__ __launch_bounds__(128) void lstm_step(
    const float* __restrict__ xp0, const float* __restrict__ xp1,
    const float* __restrict__ U0,  const float* __restrict__ U1,
    const float* __restrict__ h00, const float* __restrict__ h01,
    float* __restrict__ c0p, float* __restrict__ c1p, int cstr,
    float* __restrict__ o0,  float* __restrict__ o1,  int ostr,
    int t, int rev1)
{
    const int dir = blockIdx.y;
    const float* xp = dir ? xp1 : xp0;
    const float* U  = dir ? U1  : U0;
    const float* h0 = dir ? h01 : h00;
    float* cbuf     = dir ? c1p : c0p;
    float* hs       = dir ? o1  : o0;
    const int rev   = dir ? rev1 : 0;

    const int tt    = rev ? (TN - 1 - t) : t;
    const int tprev = rev ? (tt + 1) : (tt - 1);
    const float* hp;
    int hstr;
    if (t == 0) { hp = h0; hstr = HH; }
    else        { hp = hs + (size_t)tprev * ostr; hstr = TN * ostr; }

    const int j0 = blockIdx.x * 8;

    __shared__ float hsm[32][36];   // [k][b]  (pad 36 -> float4-aligned rows)
    __shared__ float usm[32][33];   // [k][r]
    __shared__ float gsm[32][33];   // [r][b]; r = gate*8 + unit

    const int tid = threadIdx.x;
    const int rr = tid >> 3;          // 0..15 -> rows rr, rr+16
    const int b0 = (tid & 7) * 4;     // batches b0..b0+3

    // load mapping: each thread loads one 8-float chunk of one row per matrix
    const int lr = tid >> 2;          // 0..31
    const int lk = (tid & 3) * 8;     // 0,8,16,24
    const int ugrow = ((lr >> 3) * HH) + j0 + (lr & 7);  // gate*512 + j0 + unit

    float acc[2][4] = {{0.f,0.f,0.f,0.f},{0.f,0.f,0.f,0.f}};

    for (int k0 = 0; k0 < HH; k0 += 32) {
        {
            const float* src = hp + (size_t)lr * hstr + k0 + lk;
            float4 v0 = *(const float4*)(src);
            float4 v1 = *(const float4*)(src + 4);
            hsm[lk+0][lr] = v0.x; hsm[lk+1][lr] = v0.y; hsm[lk+2][lr] = v0.z; hsm[lk+3][lr] = v0.w;
            hsm[lk+4][lr] = v1.x; hsm[lk+5][lr] = v1.y; hsm[lk+6][lr] = v1.z; hsm[lk+7][lr] = v1.w;
            const float* us = U + (size_t)ugrow * HH + k0 + lk;
            float4 u0 = *(const float4*)(us);
            float4 u1 = *(const float4*)(us + 4);
            usm[lk+0][lr] = u0.x; usm[lk+1][lr] = u0.y; usm[lk+2][lr] = u0.z; usm[lk+3][lr] = u0.w;
            usm[lk+4][lr] = u1.x; usm[lk+5][lr] = u1.y; usm[lk+6][lr] = u1.z; usm[lk+7][lr] = u1.w;
        }
        __syncthreads();
#pragma unroll
        for (int kk = 0; kk < 32; kk++) {
            float4 hv = *(const float4*)&hsm[kk][b0];
            float ua = usm[kk][rr];
            float ub = usm[kk][rr + 16];
            acc[0][0] += ua * hv.x; acc[0][1] += ua * hv.y;
            acc[0][2] += ua * hv.z; acc[0][3] += ua * hv.w;
            acc[1][0] += ub * hv.x; acc[1][1] += ub * hv.y;
            acc[1][2] += ub * hv.z; acc[1][3] += ub * hv.w;
        }
        __syncthreads();
    }

#pragma unroll
    for (int i = 0; i < 4; i++) {
        gsm[rr][b0 + i]      = acc[0][i];
        gsm[rr + 16][b0 + i] = acc[1][i];
    }
    __syncthreads();

    // pointwise cell update: 256 cells (8 units x 32 batches), 2 per thread
#pragma unroll
    for (int cix = tid; cix < 256; cix += 128) {
        int u = cix >> 5;
        int b = cix & 31;
        size_t xbase = ((size_t)b * TN + tt) * H4 + j0 + u;
        float gi = gsm[u][b]      + xp[xbase];
        float gf = gsm[8 + u][b]  + xp[xbase + 512];
        float gg = gsm[16 + u][b] + xp[xbase + 1024];
        float go = gsm[24 + u][b] + xp[xbase + 1536];
        float si = 1.f / (1.f + expf(-gi));
        float sf = 1.f / (1.f + expf(-gf));
        float so = 1.f / (1.f + expf(-go));
        float tg = tanhf(gg);
        float* cp = cbuf + (size_t)b * cstr + j0 + u;
        float c = sf * (*cp) + si * tg;
        *cp = c;
        hs[((size_t)b * TN + tt) * ostr + j0 + u] = so * tanhf(c);
    }
}

// gather hT = concat(h_fwd[t=95], h_bwd[t=0]) per encoder layer into [B,1024] rows
__global__ void gather_hT(int n) {
    int i = blockIdx.x * blockDim.x + threadIdx.x;
    if (i >= n) return;
    int l = i >> 15;             // layer
    int r = i & 32767;
    int b = r >> 10;
    int j = r & 1023;
    const float* src = l ? d_x2 : d_x1;
    int tt = (j < 512) ? (SS - 1) : 0;
    float v = src[((size_t)b * SS + tt) * H2 + j];
    (l ? d_ehT1 : d_ehT0)[b * H2 + j] = v;
}

// ---------------- attention + concat ----------------
// one block per (b,t): energies over s (masked), softmax, context, write combined
__global__ __launch_bounds__(128) void attn_kernel(
    const float* __restrict__ y, const float* __restrict__ enc,
    const int* __restrict__ src_seq, float* __restrict__ comb)
{
    const int bt = blockIdx.x;
    const int b = bt / TN;
    __shared__ float ysm[HH];
    __shared__ float esm[SS];
    __shared__ float red[1];
    const int tid = threadIdx.x;
    const float* yrow = y + (size_t)bt * HH;
#pragma unroll
    for (int i = 0; i < 4; i++) ysm[tid + i * 128] = yrow[tid + i * 128];
    __syncthreads();

    const int lane = tid & 31, w = tid >> 5;
    for (int s = w; s < SS; s += 4) {
        const float* er = enc + ((size_t)b * SS + s) * HH;
        float p = 0.f;
        for (int d = lane; d < HH; d += 32) p += ysm[d] * er[d];
#pragma unroll
        for (int off = 16; off; off >>= 1) p += __shfl_xor_sync(0xffffffffu, p, off);
        if (lane == 0) esm[s] = (src_seq[b * SS + s] != 0) ? p : -1e10f;
    }
    __syncthreads();

    if (w == 0) {
        float m = -1e30f;
        for (int s = lane; s < SS; s += 32) m = fmaxf(m, esm[s]);
#pragma unroll
        for (int off = 16; off; off >>= 1) m = fmaxf(m, __shfl_xor_sync(0xffffffffu, m, off));
        float sum = 0.f;
        for (int s = lane; s < SS; s += 32) { float e = expf(esm[s] - m); esm[s] = e; sum += e; }
#pragma unroll
        for (int off = 16; off; off >>= 1) sum += __shfl_xor_sync(0xffffffffu, sum, off);
        if (lane == 0) red[0] = 1.f / sum;
    }
    __syncthreads();

    const float inv = red[0];
    const int d = tid * 4;
    float4 ctx = make_float4(0.f, 0.f, 0.f, 0.f);
    for (int s = 0; s < SS; s++) {
        float a = esm[s] * inv;
        float4 ev = *(const float4*)(enc + ((size_t)b * SS + s) * HH + d);
        ctx.x += a * ev.x; ctx.y += a * ev.y; ctx.z += a * ev.z; ctx.w += a * ev.w;
    }
    float* crow = comb + (size_t)bt * H2;
#pragma unroll
    for (int i = 0; i < 4; i++) crow[tid + i * 128] = ysm[tid + i * 128];
    *(float4*)(crow + HH + d) = ctx;
}

// ---------------- host launcher ----------------
static float* sym(const void* s) {
    void* p = nullptr;
    cudaGetSymbolAddress(&p, s);
    return (float*)p;
}

extern "C" void kernel_launch(void* const* d_in, const int* in_sizes, int n_in,
                              void* d_out, int out_size) {
    const int*   src_seq = (const int*)d_in[0];
    const int*   trg_seq = (const int*)d_in[1];
    const float* src_emb = (const float*)d_in[2];
    const float* trg_emb = (const float*)d_in[3];
    const float* eW0f = (const float*)d_in[4];
    const float* eU0f = (const float*)d_in[5];
    const float* eb0f = (const float*)d_in[6];
    const float* eW0b = (const float*)d_in[7];
    const float* eU0b = (const float*)d_in[8];
    const float* eb0b = (const float*)d_in[9];
    const float* eW1f = (const float*)d_in[10];
    const float* eU1f = (const float*)d_in[11];
    const float* eb1f = (const float*)d_in[12];
    const float* eW1b = (const float*)d_in[13];
    const float* eU1b = (const float*)d_in[14];
    const float* eb1b = (const float*)d_in[15];
    const float* out_W = (const float*)d_in[16];
    const float* out_b = (const float*)d_in[17];
    const float* hpW  = (const float*)d_in[18];
    const float* hpb  = (const float*)d_in[19];
    const float* cpW  = (const float*)d_in[20];
    const float* cpb  = (const float*)d_in[21];
    const float* dW0  = (const float*)d_in[22];
    const float* dU0  = (const float*)d_in[23];
    const float* db0  = (const float*)d_in[24];
    const float* dW1  = (const float*)d_in[25];
    const float* dU1  = (const float*)d_in[26];
    const float* db1  = (const float*)d_in[27];
    const float* fcW  = (const float*)d_in[28];
    const float* fcb  = (const float*)d_in[29];
    float* out = (float*)d_out;

    float* xsrc = sym(d_xsrc);
    float* ytrg = sym(d_ytrg);
    float* xpf  = sym(d_xpf);
    float* xpb  = sym(d_xpb);
    float* x1   = sym(d_x1);
    float* x2   = sym(d_x2);
    float* enc  = sym(d_enc);
    float* y1   = sym(d_y1);
    float* y2   = sym(d_y2);
    float* comb = sym(d_comb);
    float* ecT0 = sym(d_ecT0);
    float* ecT1 = sym(d_ecT1);
    float* ehT0 = sym(d_ehT0);
    float* ehT1 = sym(d_ehT1);
    float* dh0  = sym(d_dh0);
    float* dh1  = sym(d_dh1);
    float* dc0  = sym(d_dc0);
    float* dc1  = sym(d_dc1);
    float* zer  = sym(d_zeros);

    // zero initial states (c buffers are updated in place every replay)
    zero_kernel<<<(BB*HH + 255)/256, 256>>>(zer, BB*HH);
    zero_kernel<<<(BB*H2 + 255)/256, 256>>>(ecT0, BB*H2);
    zero_kernel<<<(BB*H2 + 255)/256, 256>>>(ecT1, BB*H2);

    // embeddings
    embed_kernel<<<(BB*SS*EE + 255)/256, 256>>>(xsrc, src_emb, src_seq, BB*SS*EE);
    embed_kernel<<<(BB*TN*EE + 255)/256, 256>>>(ytrg, trg_emb, trg_seq, BB*TN*EE);

    const dim3 gXP(H4/128, (BB*SS + 127)/128);   // (16, 24)
    const dim3 gENC(HH/128, (BB*SS + 127)/128);  // (4, 24)
    const dim3 gPROJ(HH/128, 1);                 // (4, 1)
    const dim3 gFC(VV/128, (BB*TN + 127)/128);   // (250, 24)

    // ===== encoder layer 0 =====
    sgemm_bias_nt<<<gXP, 256>>>(xsrc, eW0f, eb0f, xpf, BB*SS, H4, EE);
    sgemm_bias_nt<<<gXP, 256>>>(xsrc, eW0b, eb0b, xpb, BB*SS, H4, EE);
    for (int t = 0; t < TN; t++)
        lstm_step<<<dim3(64, 2), 128>>>(xpf, xpb, eU0f, eU0b, zer, zer,
                                        ecT0, ecT0 + 512, H2,
                                        x1, x1 + 512, H2, t, 1);

    // ===== encoder layer 1 =====
    sgemm_bias_nt<<<gXP, 256>>>(x1, eW1f, eb1f, xpf, BB*SS, H4, H2);
    sgemm_bias_nt<<<gXP, 256>>>(x1, eW1b, eb1b, xpb, BB*SS, H4, H2);
    for (int t = 0; t < TN; t++)
        lstm_step<<<dim3(64, 2), 128>>>(xpf, xpb, eU1f, eU1b, zer, zer,
                                        ecT1, ecT1 + 512, H2,
                                        x2, x2 + 512, H2, t, 1);

    // encoder output projection
    sgemm_bias_nt<<<gENC, 256>>>(x2, out_W, out_b, enc, BB*SS, HH, H2);

    // final-state gather + decoder init projections
    gather_hT<<<(2*BB*H2 + 255)/256, 256>>>(2*BB*H2);
    sgemm_bias_nt<<<gPROJ, 256>>>(ehT0, hpW,           hpb,       dh0, BB, HH, H2);
    sgemm_bias_nt<<<gPROJ, 256>>>(ehT1, hpW + HH*H2,   hpb + HH,  dh1, BB, HH, H2);
    sgemm_bias_nt<<<gPROJ, 256>>>(ecT0, cpW,           cpb,       dc0, BB, HH, H2);
    sgemm_bias_nt<<<gPROJ, 256>>>(ecT1, cpW + HH*H2,   cpb + HH,  dc1, BB, HH, H2);

    // ===== decoder layer 0 =====
    sgemm_bias_nt<<<gXP, 256>>>(ytrg, dW0, db0, xpf, BB*TN, H4, EE);
    for (int t = 0; t < TN; t++)
        lstm_step<<<dim3(64, 1), 128>>>(xpf, nullptr, dU0, nullptr, dh0, nullptr,
                                        dc0, nullptr, HH,
                                        y1, nullptr, HH, t, 0);

    // ===== decoder layer 1 =====
    sgemm_bias_nt<<<gXP, 256>>>(y1, dW1, db1, xpf, BB*TN, H4, HH);
    for (int t = 0; t < TN; t++)
        lstm_step<<<dim3(64, 1), 128>>>(xpf, nullptr, dU1, nullptr, dh1, nullptr,
                                        dc1, nullptr, HH,
                                        y2, nullptr, HH, t, 0);

    // ===== attention + concat =====
    attn_kernel<<<BB*TN, 128>>>(y2, enc, src_seq, comb);

    // ===== final FC (dominant GEMM) =====
    sgemm_bias_nt<<<gFC, 256>>>(comb, fcW, fcb, out, BB*TN, VV, H2);
}

// round 6
// speedup vs baseline: 1.0758x; 1.0758x over previous
#include <cuda_runtime.h>
#include <math.h>
#include <mma.h>
using namespace nvcuda;

#define BB 32
#define SS 96
#define TN 96
#define EE 256
#define HH 512
#define H4 2048
#define H2 1024
#define VV 32000

// ---------------- static scratch (no allocations) ----------------
__device__ float d_xsrc[BB*SS*EE];
__device__ float d_ytrg[BB*TN*EE];
__device__ float d_xpf[BB*SS*H4];
__device__ float d_xpb[BB*SS*H4];
__device__ float d_x1[BB*SS*H2];
__device__ float d_x2[BB*SS*H2];
__device__ float d_enc[BB*SS*HH];
__device__ float d_y1[BB*TN*HH];
__device__ float d_y2[BB*TN*HH];
__device__ float d_comb[BB*TN*H2];
__device__ float d_ecT0[BB*H2];   // encoder layer0 cell state, concat(f,b)
__device__ float d_ecT1[BB*H2];
__device__ float d_ehT0[BB*H2];   // encoder layer0 final h, concat(f,b)
__device__ float d_ehT1[BB*H2];
__device__ float d_dh0[BB*HH];    // decoder initial h per layer
__device__ float d_dh1[BB*HH];
__device__ float d_dc0[BB*HH];    // decoder cell state (init = c0 proj)
__device__ float d_dc1[BB*HH];
__device__ float d_zeros[BB*HH];

// ---------------- helpers ----------------
__global__ void zero_kernel(float* __restrict__ p, int n) {
    int i = blockIdx.x * blockDim.x + threadIdx.x;
    if (i < n) p[i] = 0.f;
}

__global__ void embed_kernel(float* __restrict__ out, const float* __restrict__ emb,
                             const int* __restrict__ seq, int n) {
    int i = blockIdx.x * blockDim.x + threadIdx.x;
    if (i < n) {
        int tok = seq[i >> 8];                      // E = 256
        out[i] = emb[(size_t)tok * EE + (i & 255)];
    }
}

// ---------------- fp32 SGEMM (kept for everything feeding the recurrences) ----------------
// C[M,N] = A[M,K] @ W[N,K]^T + bias[N]; K%16==0, N%128==0; M guarded.
__global__ __launch_bounds__(256) void sgemm_bias_nt(
    const float* __restrict__ A, const float* __restrict__ W,
    const float* __restrict__ bias, float* __restrict__ C,
    int M, int N, int K)
{
    __shared__ float As[16][132];
    __shared__ float Ws[16][132];
    const int bm = blockIdx.y * 128;
    const int bn = blockIdx.x * 128;
    const int tid = threadIdx.x;
    const int trow = (tid >> 4) * 8;
    const int tcol = (tid & 15) * 8;

    float acc[8][8];
#pragma unroll
    for (int i = 0; i < 8; i++)
#pragma unroll
        for (int j = 0; j < 8; j++) acc[i][j] = 0.f;

    for (int k0 = 0; k0 < K; k0 += 16) {
#pragma unroll
        for (int i = 0; i < 2; i++) {
            int q = tid + i * 256;
            int r = q >> 2;
            int c = (q & 3) * 4;
            float4 v = make_float4(0.f, 0.f, 0.f, 0.f);
            if (bm + r < M) v = *(const float4*)(A + (size_t)(bm + r) * K + k0 + c);
            As[c + 0][r] = v.x; As[c + 1][r] = v.y; As[c + 2][r] = v.z; As[c + 3][r] = v.w;
            float4 u = *(const float4*)(W + (size_t)(bn + r) * K + k0 + c);
            Ws[c + 0][r] = u.x; Ws[c + 1][r] = u.y; Ws[c + 2][r] = u.z; Ws[c + 3][r] = u.w;
        }
        __syncthreads();
#pragma unroll
        for (int kk = 0; kk < 16; kk++) {
            float4 a0 = *(const float4*)&As[kk][trow];
            float4 a1 = *(const float4*)&As[kk][trow + 4];
            float4 b0 = *(const float4*)&Ws[kk][tcol];
            float4 b1 = *(const float4*)&Ws[kk][tcol + 4];
            float av[8] = {a0.x, a0.y, a0.z, a0.w, a1.x, a1.y, a1.z, a1.w};
            float bv[8] = {b0.x, b0.y, b0.z, b0.w, b1.x, b1.y, b1.z, b1.w};
#pragma unroll
            for (int i = 0; i < 8; i++)
#pragma unroll
                for (int j = 0; j < 8; j++) acc[i][j] += av[i] * bv[j];
        }
        __syncthreads();
    }

    float bb[8];
#pragma unroll
    for (int j = 0; j < 8; j++) bb[j] = bias[bn + tcol + j];
#pragma unroll
    for (int i = 0; i < 8; i++) {
        int r = bm + trow + i;
        if (r < M) {
            float* cp = C + (size_t)r * N + bn + tcol;
#pragma unroll
            for (int j = 0; j < 8; j += 4) {
                float4 v;
                v.x = acc[i][j + 0] + bb[j + 0];
                v.y = acc[i][j + 1] + bb[j + 1];
                v.z = acc[i][j + 2] + bb[j + 2];
                v.w = acc[i][j + 3] + bb[j + 3];
                *(float4*)(cp + j) = v;
            }
        }
    }
}

// ---------------- TF32 tensor-core GEMM for the dominant FC ----------------
// C[M,N] = A[M,K] @ W[N,K]^T + bias[N].  Requires M%128==0, N%128==0, K%32==0.
// 128x128 block tile, 8 warps of 32x64 (2x4 wmma m16n16k8 tiles), K staged 32 wide.
// Grid: (M/128, N/128) with M the FAST dim so a wave shares W tiles in L2.
__global__ __launch_bounds__(256) void gemm_tf32_fc(
    const float* __restrict__ A, const float* __restrict__ W,
    const float* __restrict__ bias, float* __restrict__ C,
    int M, int N, int K)
{
    __shared__ float As[128 * 40];
    __shared__ float Bs[128 * 40];
    const int bm = blockIdx.x * 128;
    const int bn = blockIdx.y * 128;
    const int tid  = threadIdx.x;
    const int warp = tid >> 5;
    const int lane = tid & 31;
    const int wm = warp & 3;    // 0..3  -> 32-row strip
    const int wn = warp >> 2;   // 0..1  -> 64-col strip

    wmma::fragment<wmma::accumulator, 16, 16, 8, float> c[2][4];
#pragma unroll
    for (int i = 0; i < 2; i++)
#pragma unroll
        for (int j = 0; j < 4; j++) wmma::fill_fragment(c[i][j], 0.f);

    const int lr = tid >> 1;           // 0..127
    const int lc = (tid & 1) * 16;     // 0 or 16

    for (int k0 = 0; k0 < K; k0 += 32) {
        const float* ap = A + (size_t)(bm + lr) * K + k0 + lc;
        const float* wp = W + (size_t)(bn + lr) * K + k0 + lc;
        float* asd = As + lr * 40 + lc;
        float* bsd = Bs + lr * 40 + lc;
#pragma unroll
        for (int q = 0; q < 4; q++) {
            *(float4*)(asd + q * 4) = *(const float4*)(ap + q * 4);
            *(float4*)(bsd + q * 4) = *(const float4*)(wp + q * 4);
        }
        __syncthreads();

#pragma unroll
        for (int kk = 0; kk < 4; kk++) {
            wmma::fragment<wmma::matrix_a, 16, 16, 8, wmma::precision::tf32, wmma::row_major> a[2];
            wmma::fragment<wmma::matrix_b, 16, 16, 8, wmma::precision::tf32, wmma::col_major> b[4];
#pragma unroll
            for (int i = 0; i < 2; i++) {
                wmma::load_matrix_sync(a[i], As + (wm * 32 + i * 16) * 40 + kk * 8, 40);
#pragma unroll
                for (int e = 0; e < a[i].num_elements; e++)
                    a[i].x[e] = wmma::__float_to_tf32(a[i].x[e]);
            }
#pragma unroll
            for (int j = 0; j < 4; j++) {
                wmma::load_matrix_sync(b[j], Bs + (wn * 64 + j * 16) * 40 + kk * 8, 40);
#pragma unroll
                for (int e = 0; e < b[j].num_elements; e++)
                    b[j].x[e] = wmma::__float_to_tf32(b[j].x[e]);
            }
#pragma unroll
            for (int i = 0; i < 2; i++)
#pragma unroll
                for (int j = 0; j < 4; j++)
                    wmma::mma_sync(c[i][j], a[i], b[j], c[i][j]);
        }
        __syncthreads();
    }

    // epilogue: stage each 16x16 fragment through per-warp smem, fuse bias
    float* wbuf = As + warp * (16 * 20);   // 320 floats per warp (As is free now)
    const int er = lane >> 1;
    const int ec = (lane & 1) * 8;
#pragma unroll
    for (int i = 0; i < 2; i++) {
#pragma unroll
        for (int j = 0; j < 4; j++) {
            wmma::store_matrix_sync(wbuf, c[i][j], 20, wmma::mem_row_major);
            __syncwarp();
            const int gr = bm + wm * 32 + i * 16 + er;
            const int gc = bn + wn * 64 + j * 16 + ec;
            const float* bp = bias + gc;
            float* dst = C + (size_t)gr * N + gc;
            float4 v0, v1;
            v0.x = wbuf[er * 20 + ec + 0] + bp[0];
            v0.y = wbuf[er * 20 + ec + 1] + bp[1];
            v0.z = wbuf[er * 20 + ec + 2] + bp[2];
            v0.w = wbuf[er * 20 + ec + 3] + bp[3];
            v1.x = wbuf[er * 20 + ec + 4] + bp[4];
            v1.y = wbuf[er * 20 + ec + 5] + bp[5];
            v1.z = wbuf[er * 20 + ec + 6] + bp[6];
            v1.w = wbuf[er * 20 + ec + 7] + bp[7];
            *(float4*)(dst)     = v0;
            *(float4*)(dst + 4) = v1;
            __syncwarp();
        }
    }
}

// ---------------- one LSTM timestep ----------------
__global__ __launch_bounds__(128) void lstm_step(
    const float* __restrict__ xp0, const float* __restrict__ xp1,
    const float* __restrict__ U0,  const float* __restrict__ U1,
    const float* __restrict__ h00, const float* __restrict__ h01,
    float* __restrict__ c0p, float* __restrict__ c1p, int cstr,
    float* __restrict__ o0,  float* __restrict__ o1,  int ostr,
    int t, int rev1)
{
    const int dir = blockIdx.y;
    const float* xp = dir ? xp1 : xp0;
    const float* U  = dir ? U1  : U0;
    const float* h0 = dir ? h01 : h00;
    float* cbuf     = dir ? c1p : c0p;
    float* hs       = dir ? o1  : o0;
    const int rev   = dir ? rev1 : 0;

    const int tt    = rev ? (TN - 1 - t) : t;
    const int tprev = rev ? (tt + 1) : (tt - 1);
    const float* hp;
    int hstr;
    if (t == 0) { hp = h0; hstr = HH; }
    else        { hp = hs + (size_t)tprev * ostr; hstr = TN * ostr; }

    const int j0 = blockIdx.x * 8;

    __shared__ float hsm[32][36];
    __shared__ float usm[32][33];
    __shared__ float gsm[32][33];

    const int tid = threadIdx.x;
    const int rr = tid >> 3;
    const int b0 = (tid & 7) * 4;

    const int lr = tid >> 2;
    const int lk = (tid & 3) * 8;
    const int ugrow = ((lr >> 3) * HH) + j0 + (lr & 7);

    float acc[2][4] = {{0.f,0.f,0.f,0.f},{0.f,0.f,0.f,0.f}};

    for (int k0 = 0; k0 < HH; k0 += 32) {
        {
            const float* src = hp + (size_t)lr * hstr + k0 + lk;
            float4 v0 = *(const float4*)(src);
            float4 v1 = *(const float4*)(src + 4);
            hsm[lk+0][lr] = v0.x; hsm[lk+1][lr] = v0.y; hsm[lk+2][lr] = v0.z; hsm[lk+3][lr] = v0.w;
            hsm[lk+4][lr] = v1.x; hsm[lk+5][lr] = v1.y; hsm[lk+6][lr] = v1.z; hsm[lk+7][lr] = v1.w;
            const float* us = U + (size_t)ugrow * HH + k0 + lk;
            float4 u0 = *(const float4*)(us);
            float4 u1 = *(const float4*)(us + 4);
            usm[lk+0][lr] = u0.x; usm[lk+1][lr] = u0.y; usm[lk+2][lr] = u0.z; usm[lk+3][lr] = u0.w;
            usm[lk+4][lr] = u1.x; usm[lk+5][lr] = u1.y; usm[lk+6][lr] = u1.z; usm[lk+7][lr] = u1.w;
        }
        __syncthreads();
#pragma unroll
        for (int kk = 0; kk < 32; kk++) {
            float4 hv = *(const float4*)&hsm[kk][b0];
            float ua = usm[kk][rr];
            float ub = usm[kk][rr + 16];
            acc[0][0] += ua * hv.x; acc[0][1] += ua * hv.y;
            acc[0][2] += ua * hv.z; acc[0][3] += ua * hv.w;
            acc[1][0] += ub * hv.x; acc[1][1] += ub * hv.y;
            acc[1][2] += ub * hv.z; acc[1][3] += ub * hv.w;
        }
        __syncthreads();
    }

#pragma unroll
    for (int i = 0; i < 4; i++) {
        gsm[rr][b0 + i]      = acc[0][i];
        gsm[rr + 16][b0 + i] = acc[1][i];
    }
    __syncthreads();

#pragma unroll
    for (int cix = tid; cix < 256; cix += 128) {
        int u = cix >> 5;
        int b = cix & 31;
        size_t xbase = ((size_t)b * TN + tt) * H4 + j0 + u;
        float gi = gsm[u][b]      + xp[xbase];
        float gf = gsm[8 + u][b]  + xp[xbase + 512];
        float gg = gsm[16 + u][b] + xp[xbase + 1024];
        float go = gsm[24 + u][b] + xp[xbase + 1536];
        float si = 1.f / (1.f + expf(-gi));
        float sf = 1.f / (1.f + expf(-gf));
        float so = 1.f / (1.f + expf(-go));
        float tg = tanhf(gg);
        float* cp = cbuf + (size_t)b * cstr + j0 + u;
        float c = sf * (*cp) + si * tg;
        *cp = c;
        hs[((size_t)b * TN + tt) * ostr + j0 + u] = so * tanhf(c);
    }
}

__global__ void gather_hT(int n) {
    int i = blockIdx.x * blockDim.x + threadIdx.x;
    if (i >= n) return;
    int l = i >> 15;
    int r = i & 32767;
    int b = r >> 10;
    int j = r & 1023;
    const float* src = l ? d_x2 : d_x1;
    int tt = (j < 512) ? (SS - 1) : 0;
    float v = src[((size_t)b * SS + tt) * H2 + j];
    (l ? d_ehT1 : d_ehT0)[b * H2 + j] = v;
}

// ---------------- attention + concat ----------------
__global__ __launch_bounds__(128) void attn_kernel(
    const float* __restrict__ y, const float* __restrict__ enc,
    const int* __restrict__ src_seq, float* __restrict__ comb)
{
    const int bt = blockIdx.x;
    const int b = bt / TN;
    __shared__ float ysm[HH];
    __shared__ float esm[SS];
    __shared__ float red[1];
    const int tid = threadIdx.x;
    const float* yrow = y + (size_t)bt * HH;
#pragma unroll
    for (int i = 0; i < 4; i++) ysm[tid + i * 128] = yrow[tid + i * 128];
    __syncthreads();

    const int lane = tid & 31, w = tid >> 5;
    for (int s = w; s < SS; s += 4) {
        const float* er = enc + ((size_t)b * SS + s) * HH;
        float p = 0.f;
        for (int d = lane; d < HH; d += 32) p += ysm[d] * er[d];
#pragma unroll
        for (int off = 16; off; off >>= 1) p += __shfl_xor_sync(0xffffffffu, p, off);
        if (lane == 0) esm[s] = (src_seq[b * SS + s] != 0) ? p : -1e10f;
    }
    __syncthreads();

    if (w == 0) {
        float m = -1e30f;
        for (int s = lane; s < SS; s += 32) m = fmaxf(m, esm[s]);
#pragma unroll
        for (int off = 16; off; off >>= 1) m = fmaxf(m, __shfl_xor_sync(0xffffffffu, m, off));
        float sum = 0.f;
        for (int s = lane; s < SS; s += 32) { float e = expf(esm[s] - m); esm[s] = e; sum += e; }
#pragma unroll
        for (int off = 16; off; off >>= 1) sum += __shfl_xor_sync(0xffffffffu, sum, off);
        if (lane == 0) red[0] = 1.f / sum;
    }
    __syncthreads();

    const float inv = red[0];
    const int d = tid * 4;
    float4 ctx = make_float4(0.f, 0.f, 0.f, 0.f);
    for (int s = 0; s < SS; s++) {
        float a = esm[s] * inv;
        float4 ev = *(const float4*)(enc + ((size_t)b * SS + s) * HH + d);
        ctx.x += a * ev.x; ctx.y += a * ev.y; ctx.z += a * ev.z; ctx.w += a * ev.w;
    }
    float* crow = comb + (size_t)bt * H2;
#pragma unroll
    for (int i = 0; i < 4; i++) crow[tid + i * 128] = ysm[tid + i * 128];
    *(float4*)(crow + HH + d) = ctx;
}

// ---------------- host launcher ----------------
static float* sym(const void* s) {
    void* p = nullptr;
    cudaGetSymbolAddress(&p, s);
    return (float*)p;
}

extern "C" void kernel_launch(void* const* d_in, const int* in_sizes, int n_in,
                              void* d_out, int out_size) {
    const int*   src_seq = (const int*)d_in[0];
    const int*   trg_seq = (const int*)d_in[1];
    const float* src_emb = (const float*)d_in[2];
    const float* trg_emb = (const float*)d_in[3];
    const float* eW0f = (const float*)d_in[4];
    const float* eU0f = (const float*)d_in[5];
    const float* eb0f = (const float*)d_in[6];
    const float* eW0b = (const float*)d_in[7];
    const float* eU0b = (const float*)d_in[8];
    const float* eb0b = (const float*)d_in[9];
    const float* eW1f = (const float*)d_in[10];
    const float* eU1f = (const float*)d_in[11];
    const float* eb1f = (const float*)d_in[12];
    const float* eW1b = (const float*)d_in[13];
    const float* eU1b = (const float*)d_in[14];
    const float* eb1b = (const float*)d_in[15];
    const float* out_W = (const float*)d_in[16];
    const float* out_b = (const float*)d_in[17];
    const float* hpW  = (const float*)d_in[18];
    const float* hpb  = (const float*)d_in[19];
    const float* cpW  = (const float*)d_in[20];
    const float* cpb  = (const float*)d_in[21];
    const float* dW0  = (const float*)d_in[22];
    const float* dU0  = (const float*)d_in[23];
    const float* db0  = (const float*)d_in[24];
    const float* dW1  = (const float*)d_in[25];
    const float* dU1  = (const float*)d_in[26];
    const float* db1  = (const float*)d_in[27];
    const float* fcW  = (const float*)d_in[28];
    const float* fcb  = (const float*)d_in[29];
    float* out = (float*)d_out;

    float* xsrc = sym(d_xsrc);
    float* ytrg = sym(d_ytrg);
    float* xpf  = sym(d_xpf);
    float* xpb  = sym(d_xpb);
    float* x1   = sym(d_x1);
    float* x2   = sym(d_x2);
    float* enc  = sym(d_enc);
    float* y1   = sym(d_y1);
    float* y2   = sym(d_y2);
    float* comb = sym(d_comb);
    float* ecT0 = sym(d_ecT0);
    float* ecT1 = sym(d_ecT1);
    float* ehT0 = sym(d_ehT0);
    float* ehT1 = sym(d_ehT1);
    float* dh0  = sym(d_dh0);
    float* dh1  = sym(d_dh1);
    float* dc0  = sym(d_dc0);
    float* dc1  = sym(d_dc1);
    float* zer  = sym(d_zeros);

    zero_kernel<<<(BB*HH + 255)/256, 256>>>(zer, BB*HH);
    zero_kernel<<<(BB*H2 + 255)/256, 256>>>(ecT0, BB*H2);
    zero_kernel<<<(BB*H2 + 255)/256, 256>>>(ecT1, BB*H2);

    embed_kernel<<<(BB*SS*EE + 255)/256, 256>>>(xsrc, src_emb, src_seq, BB*SS*EE);
    embed_kernel<<<(BB*TN*EE + 255)/256, 256>>>(ytrg, trg_emb, trg_seq, BB*TN*EE);

    const dim3 gXP(H4/128, (BB*SS + 127)/128);   // (16, 24)
    const dim3 gENC(HH/128, (BB*SS + 127)/128);  // (4, 24)
    const dim3 gPROJ(HH/128, 1);                 // (4, 1)
    const dim3 gFC((BB*TN)/128, VV/128);         // (24, 250)  M-fast for L2 reuse of W

    // ===== encoder layer 0 =====
    sgemm_bias_nt<<<gXP, 256>>>(xsrc, eW0f, eb0f, xpf, BB*SS, H4, EE);
    sgemm_bias_nt<<<gXP, 256>>>(xsrc, eW0b, eb0b, xpb, BB*SS, H4, EE);
    for (int t = 0; t < TN; t++)
        lstm_step<<<dim3(64, 2), 128>>>(xpf, xpb, eU0f, eU0b, zer, zer,
                                        ecT0, ecT0 + 512, H2,
                                        x1, x1 + 512, H2, t, 1);

    // ===== encoder layer 1 =====
    sgemm_bias_nt<<<gXP, 256>>>(x1, eW1f, eb1f, xpf, BB*SS, H4, H2);
    sgemm_bias_nt<<<gXP, 256>>>(x1, eW1b, eb1b, xpb, BB*SS, H4, H2);
    for (int t = 0; t < TN; t++)
        lstm_step<<<dim3(64, 2), 128>>>(xpf, xpb, eU1f, eU1b, zer, zer,
                                        ecT1, ecT1 + 512, H2,
                                        x2, x2 + 512, H2, t, 1);

    sgemm_bias_nt<<<gENC, 256>>>(x2, out_W, out_b, enc, BB*SS, HH, H2);

    gather_hT<<<(2*BB*H2 + 255)/256, 256>>>(2*BB*H2);
    sgemm_bias_nt<<<gPROJ, 256>>>(ehT0, hpW,           hpb,       dh0, BB, HH, H2);
    sgemm_bias_nt<<<gPROJ, 256>>>(ehT1, hpW + HH*H2,   hpb + HH,  dh1, BB, HH, H2);
    sgemm_bias_nt<<<gPROJ, 256>>>(ecT0, cpW,           cpb,       dc0, BB, HH, H2);
    sgemm_bias_nt<<<gPROJ, 256>>>(ecT1, cpW + HH*H2,   cpb + HH,  dc1, BB, HH, H2);

    // ===== decoder layer 0 =====
    sgemm_bias_nt<<<gXP, 256>>>(ytrg, dW0, db0, xpf, BB*TN, H4, EE);
    for (int t = 0; t < TN; t++)
        lstm_step<<<dim3(64, 1), 128>>>(xpf, nullptr, dU0, nullptr, dh0, nullptr,
                                        dc0, nullptr, HH,
                                        y1, nullptr, HH, t, 0);

    // ===== decoder layer 1 =====
    sgemm_bias_nt<<<gXP, 256>>>(y1, dW1, db1, xpf, BB*TN, H4, HH);
    for (int t = 0; t < TN; t++)
        lstm_step<<<dim3(64, 1), 128>>>(xpf, nullptr, dU1, nullptr, dh1, nullptr,
                                        dc1, nullptr, HH,
                                        y2, nullptr, HH, t, 0);

    // ===== attention + concat =====
    attn_kernel<<<BB*TN, 128>>>(y2, enc, src_seq, comb);

    // ===== final FC on tensor cores (TF32) =====
    gemm_tf32_fc<<<gFC, 256>>>(comb, fcW, fcb, out, BB*TN, VV, H2);
}

// round 7
// speedup vs baseline: 1.1098x; 1.0317x over previous
#include <cuda_runtime.h>
#include <math.h>
#include <mma.h>
using namespace nvcuda;

#define BB 32
#define SS 96
#define TN 96
#define EE 256
#define HH 512
#define H4 2048
#define H2 1024
#define VV 32000

// ---------------- static scratch (no allocations) ----------------
__device__ float d_xsrc[BB*SS*EE];
__device__ float d_ytrg[BB*TN*EE];
__device__ float d_xpf[BB*SS*H4];
__device__ float d_xpb[BB*SS*H4];
__device__ float d_x1[BB*SS*H2];
__device__ float d_x2[BB*SS*H2];
__device__ float d_enc[BB*SS*HH];
__device__ float d_y1[BB*TN*HH];
__device__ float d_y2[BB*TN*HH];
__device__ float d_comb[BB*TN*H2];
__device__ float d_ecT0[BB*H2];
__device__ float d_ecT1[BB*H2];
__device__ float d_ehT0[BB*H2];
__device__ float d_ehT1[BB*H2];
__device__ float d_dh0[BB*HH];
__device__ float d_dh1[BB*HH];
__device__ float d_dc0[BB*HH];
__device__ float d_dc1[BB*HH];
__device__ float d_zeros[BB*HH];

// ---------------- helpers ----------------
__global__ void zero_kernel(float* __restrict__ p, int n) {
    int i = blockIdx.x * blockDim.x + threadIdx.x;
    if (i < n) p[i] = 0.f;
}

__global__ void embed_kernel(float* __restrict__ out, const float* __restrict__ emb,
                             const int* __restrict__ seq, int n) {
    int i = blockIdx.x * blockDim.x + threadIdx.x;
    if (i < n) {
        int tok = seq[i >> 8];
        out[i] = emb[(size_t)tok * EE + (i & 255)];
    }
}

// ---------------- fp32 SGEMM (small projections only) ----------------
__global__ __launch_bounds__(256) void sgemm_bias_nt(
    const float* __restrict__ A, const float* __restrict__ W,
    const float* __restrict__ bias, float* __restrict__ C,
    int M, int N, int K)
{
    __shared__ float As[16][132];
    __shared__ float Ws[16][132];
    const int bm = blockIdx.y * 128;
    const int bn = blockIdx.x * 128;
    const int tid = threadIdx.x;
    const int trow = (tid >> 4) * 8;
    const int tcol = (tid & 15) * 8;

    float acc[8][8];
#pragma unroll
    for (int i = 0; i < 8; i++)
#pragma unroll
        for (int j = 0; j < 8; j++) acc[i][j] = 0.f;

    for (int k0 = 0; k0 < K; k0 += 16) {
#pragma unroll
        for (int i = 0; i < 2; i++) {
            int q = tid + i * 256;
            int r = q >> 2;
            int c = (q & 3) * 4;
            float4 v = make_float4(0.f, 0.f, 0.f, 0.f);
            if (bm + r < M) v = *(const float4*)(A + (size_t)(bm + r) * K + k0 + c);
            As[c + 0][r] = v.x; As[c + 1][r] = v.y; As[c + 2][r] = v.z; As[c + 3][r] = v.w;
            float4 u = *(const float4*)(W + (size_t)(bn + r) * K + k0 + c);
            Ws[c + 0][r] = u.x; Ws[c + 1][r] = u.y; Ws[c + 2][r] = u.z; Ws[c + 3][r] = u.w;
        }
        __syncthreads();
#pragma unroll
        for (int kk = 0; kk < 16; kk++) {
            float4 a0 = *(const float4*)&As[kk][trow];
            float4 a1 = *(const float4*)&As[kk][trow + 4];
            float4 b0 = *(const float4*)&Ws[kk][tcol];
            float4 b1 = *(const float4*)&Ws[kk][tcol + 4];
            float av[8] = {a0.x, a0.y, a0.z, a0.w, a1.x, a1.y, a1.z, a1.w};
            float bv[8] = {b0.x, b0.y, b0.z, b0.w, b1.x, b1.y, b1.z, b1.w};
#pragma unroll
            for (int i = 0; i < 8; i++)
#pragma unroll
                for (int j = 0; j < 8; j++) acc[i][j] += av[i] * bv[j];
        }
        __syncthreads();
    }

    float bb[8];
#pragma unroll
    for (int j = 0; j < 8; j++) bb[j] = bias[bn + tcol + j];
#pragma unroll
    for (int i = 0; i < 8; i++) {
        int r = bm + trow + i;
        if (r < M) {
            float* cp = C + (size_t)r * N + bn + tcol;
#pragma unroll
            for (int j = 0; j < 8; j += 4) {
                float4 v;
                v.x = acc[i][j + 0] + bb[j + 0];
                v.y = acc[i][j + 1] + bb[j + 1];
                v.z = acc[i][j + 2] + bb[j + 2];
                v.w = acc[i][j + 3] + bb[j + 3];
                *(float4*)(cp + j) = v;
            }
        }
    }
}

// ---------------- TF32 tensor-core GEMM (FC + big projections) ----------------
// C[M,N] = A[M,K] @ W[N,K]^T + bias[N].  Requires M%128==0, N%128==0, K%32==0.
// 128x128 tile, 8 warps of 32x64 (2x4 m16n16k8). tf32 conversion at staging;
// double-buffered smem k-pipeline (register-staged LDG overlaps mma).
// Dynamic smem: 4 * 5120 floats = 80 KB. Grid (M/128, N/128), M fast.
__global__ __launch_bounds__(256) void gemm_tf32(
    const float* __restrict__ A, const float* __restrict__ W,
    const float* __restrict__ bias, float* __restrict__ C,
    int M, int N, int K)
{
    extern __shared__ float sm[];
    float* Ab[2] = { sm,          sm + 5120 };
    float* Bb[2] = { sm + 10240,  sm + 15360 };

    const int bm = blockIdx.x * 128;
    const int bn = blockIdx.y * 128;
    const int tid  = threadIdx.x;
    const int warp = tid >> 5;
    const int lane = tid & 31;
    const int wm = warp & 3;
    const int wn = warp >> 2;

    wmma::fragment<wmma::accumulator, 16, 16, 8, float> c[2][4];
#pragma unroll
    for (int i = 0; i < 2; i++)
#pragma unroll
        for (int j = 0; j < 4; j++) wmma::fill_fragment(c[i][j], 0.f);

    const int lr = tid >> 1;
    const int lc = (tid & 1) * 16;
    const float* ap = A + (size_t)(bm + lr) * K + lc;
    const float* wp = W + (size_t)(bn + lr) * K + lc;

    float4 ra[4], rw[4];
#pragma unroll
    for (int q = 0; q < 4; q++) {
        ra[q] = *(const float4*)(ap + q * 4);
        rw[q] = *(const float4*)(wp + q * 4);
    }
    {
        float* ad = Ab[0] + lr * 40 + lc;
        float* bd = Bb[0] + lr * 40 + lc;
#pragma unroll
        for (int q = 0; q < 4; q++) {
            ad[q*4+0] = wmma::__float_to_tf32(ra[q].x);
            ad[q*4+1] = wmma::__float_to_tf32(ra[q].y);
            ad[q*4+2] = wmma::__float_to_tf32(ra[q].z);
            ad[q*4+3] = wmma::__float_to_tf32(ra[q].w);
            bd[q*4+0] = wmma::__float_to_tf32(rw[q].x);
            bd[q*4+1] = wmma::__float_to_tf32(rw[q].y);
            bd[q*4+2] = wmma::__float_to_tf32(rw[q].z);
            bd[q*4+3] = wmma::__float_to_tf32(rw[q].w);
        }
    }
    __syncthreads();

    const int ksteps = K >> 5;
    int cur = 0;
    for (int ks = 0; ks < ksteps; ks++) {
        const bool more = (ks + 1 < ksteps);
        if (more) {
            const float* a2 = ap + (ks + 1) * 32;
            const float* w2 = wp + (ks + 1) * 32;
#pragma unroll
            for (int q = 0; q < 4; q++) {
                ra[q] = *(const float4*)(a2 + q * 4);
                rw[q] = *(const float4*)(w2 + q * 4);
            }
        }
        const float* As = Ab[cur];
        const float* Bs = Bb[cur];
#pragma unroll
        for (int kk = 0; kk < 4; kk++) {
            wmma::fragment<wmma::matrix_a, 16, 16, 8, wmma::precision::tf32, wmma::row_major> a[2];
            wmma::fragment<wmma::matrix_b, 16, 16, 8, wmma::precision::tf32, wmma::col_major> b[4];
#pragma unroll
            for (int i = 0; i < 2; i++)
                wmma::load_matrix_sync(a[i], As + (wm * 32 + i * 16) * 40 + kk * 8, 40);
#pragma unroll
            for (int j = 0; j < 4; j++)
                wmma::load_matrix_sync(b[j], Bs + (wn * 64 + j * 16) * 40 + kk * 8, 40);
#pragma unroll
            for (int i = 0; i < 2; i++)
#pragma unroll
                for (int j = 0; j < 4; j++)
                    wmma::mma_sync(c[i][j], a[i], b[j], c[i][j]);
        }
        if (more) {
            float* ad = Ab[cur ^ 1] + lr * 40 + lc;
            float* bd = Bb[cur ^ 1] + lr * 40 + lc;
#pragma unroll
            for (int q = 0; q < 4; q++) {
                ad[q*4+0] = wmma::__float_to_tf32(ra[q].x);
                ad[q*4+1] = wmma::__float_to_tf32(ra[q].y);
                ad[q*4+2] = wmma::__float_to_tf32(ra[q].z);
                ad[q*4+3] = wmma::__float_to_tf32(ra[q].w);
                bd[q*4+0] = wmma::__float_to_tf32(rw[q].x);
                bd[q*4+1] = wmma::__float_to_tf32(rw[q].y);
                bd[q*4+2] = wmma::__float_to_tf32(rw[q].z);
                bd[q*4+3] = wmma::__float_to_tf32(rw[q].w);
            }
            __syncthreads();
            cur ^= 1;
        }
    }
    __syncthreads();

    // epilogue via per-warp smem staging, fused bias
    float* wbuf = sm + warp * 320;
    const int er = lane >> 1;
    const int ec = (lane & 1) * 8;
#pragma unroll
    for (int i = 0; i < 2; i++) {
#pragma unroll
        for (int j = 0; j < 4; j++) {
            wmma::store_matrix_sync(wbuf, c[i][j], 20, wmma::mem_row_major);
            __syncwarp();
            const int gr = bm + wm * 32 + i * 16 + er;
            const int gc = bn + wn * 64 + j * 16 + ec;
            const float* bp = bias + gc;
            float* dst = C + (size_t)gr * N + gc;
            float4 v0, v1;
            v0.x = wbuf[er * 20 + ec + 0] + bp[0];
            v0.y = wbuf[er * 20 + ec + 1] + bp[1];
            v0.z = wbuf[er * 20 + ec + 2] + bp[2];
            v0.w = wbuf[er * 20 + ec + 3] + bp[3];
            v1.x = wbuf[er * 20 + ec + 4] + bp[4];
            v1.y = wbuf[er * 20 + ec + 5] + bp[5];
            v1.z = wbuf[er * 20 + ec + 6] + bp[6];
            v1.w = wbuf[er * 20 + ec + 7] + bp[7];
            *(float4*)(dst)     = v0;
            *(float4*)(dst + 4) = v1;
            __syncwarp();
        }
    }
}

// ---------------- one LSTM timestep (256 threads) ----------------
// Grid: (64, ndir) x 256. Block owns 8 units x 4 gates (32 rows) x 32 batches.
__global__ __launch_bounds__(256) void lstm_step(
    const float* __restrict__ xp0, const float* __restrict__ xp1,
    const float* __restrict__ U0,  const float* __restrict__ U1,
    const float* __restrict__ h00, const float* __restrict__ h01,
    float* __restrict__ c0p, float* __restrict__ c1p, int cstr,
    float* __restrict__ o0,  float* __restrict__ o1,  int ostr,
    int t, int rev1)
{
    const int dir = blockIdx.y;
    const float* xp = dir ? xp1 : xp0;
    const float* U  = dir ? U1  : U0;
    const float* h0 = dir ? h01 : h00;
    float* cbuf     = dir ? c1p : c0p;
    float* hs       = dir ? o1  : o0;
    const int rev   = dir ? rev1 : 0;

    const int tt    = rev ? (TN - 1 - t) : t;
    const int tprev = rev ? (tt + 1) : (tt - 1);
    const float* hp;
    int hstr;
    if (t == 0) { hp = h0; hstr = HH; }
    else        { hp = hs + (size_t)tprev * ostr; hstr = TN * ostr; }

    const int j0 = blockIdx.x * 8;

    __shared__ float hsm[32][36];
    __shared__ float usm[32][33];
    __shared__ float gsm[32][33];

    const int tid = threadIdx.x;
    const int rr = tid >> 3;          // gate-row 0..31
    const int b0 = (tid & 7) * 4;     // batch group

    const int lr = tid >> 3;          // loader row 0..31
    const int lk = (tid & 7) * 4;     // loader col chunk
    const int ugrow = ((lr >> 3) * HH) + j0 + (lr & 7);

    float acc[4] = {0.f, 0.f, 0.f, 0.f};

    for (int k0 = 0; k0 < HH; k0 += 32) {
        {
            float4 v = *(const float4*)(hp + (size_t)lr * hstr + k0 + lk);
            hsm[lk+0][lr] = v.x; hsm[lk+1][lr] = v.y; hsm[lk+2][lr] = v.z; hsm[lk+3][lr] = v.w;
            float4 u = *(const float4*)(U + (size_t)ugrow * HH + k0 + lk);
            usm[lk+0][lr] = u.x; usm[lk+1][lr] = u.y; usm[lk+2][lr] = u.z; usm[lk+3][lr] = u.w;
        }
        __syncthreads();
#pragma unroll
        for (int kk = 0; kk < 32; kk++) {
            float4 hv = *(const float4*)&hsm[kk][b0];
            float uu = usm[kk][rr];
            acc[0] += uu * hv.x; acc[1] += uu * hv.y;
            acc[2] += uu * hv.z; acc[3] += uu * hv.w;
        }
        __syncthreads();
    }

#pragma unroll
    for (int i = 0; i < 4; i++) gsm[rr][b0 + i] = acc[i];
    __syncthreads();

    // pointwise: 256 cells, one per thread
    {
        int u = tid >> 5;
        int b = tid & 31;
        size_t xbase = ((size_t)b * TN + tt) * H4 + j0 + u;
        float gi = gsm[u][b]      + xp[xbase];
        float gf = gsm[8 + u][b]  + xp[xbase + 512];
        float gg = gsm[16 + u][b] + xp[xbase + 1024];
        float go = gsm[24 + u][b] + xp[xbase + 1536];
        float si = 1.f / (1.f + expf(-gi));
        float sf = 1.f / (1.f + expf(-gf));
        float so = 1.f / (1.f + expf(-go));
        float tg = tanhf(gg);
        float* cp = cbuf + (size_t)b * cstr + j0 + u;
        float c = sf * (*cp) + si * tg;
        *cp = c;
        hs[((size_t)b * TN + tt) * ostr + j0 + u] = so * tanhf(c);
    }
}

__global__ void gather_hT(int n) {
    int i = blockIdx.x * blockDim.x + threadIdx.x;
    if (i >= n) return;
    int l = i >> 15;
    int r = i & 32767;
    int b = r >> 10;
    int j = r & 1023;
    const float* src = l ? d_x2 : d_x1;
    int tt = (j < 512) ? (SS - 1) : 0;
    float v = src[((size_t)b * SS + tt) * H2 + j];
    (l ? d_ehT1 : d_ehT0)[b * H2 + j] = v;
}

// ---------------- attention + concat ----------------
__global__ __launch_bounds__(128) void attn_kernel(
    const float* __restrict__ y, const float* __restrict__ enc,
    const int* __restrict__ src_seq, float* __restrict__ comb)
{
    const int bt = blockIdx.x;
    const int b = bt / TN;
    __shared__ float ysm[HH];
    __shared__ float esm[SS];
    __shared__ float red[1];
    const int tid = threadIdx.x;
    const float* yrow = y + (size_t)bt * HH;
#pragma unroll
    for (int i = 0; i < 4; i++) ysm[tid + i * 128] = yrow[tid + i * 128];
    __syncthreads();

    const int lane = tid & 31, w = tid >> 5;
    for (int s = w; s < SS; s += 4) {
        const float* er = enc + ((size_t)b * SS + s) * HH;
        float p = 0.f;
        for (int d = lane; d < HH; d += 32) p += ysm[d] * er[d];
#pragma unroll
        for (int off = 16; off; off >>= 1) p += __shfl_xor_sync(0xffffffffu, p, off);
        if (lane == 0) esm[s] = (src_seq[b * SS + s] != 0) ? p : -1e10f;
    }
    __syncthreads();

    if (w == 0) {
        float m = -1e30f;
        for (int s = lane; s < SS; s += 32) m = fmaxf(m, esm[s]);
#pragma unroll
        for (int off = 16; off; off >>= 1) m = fmaxf(m, __shfl_xor_sync(0xffffffffu, m, off));
        float sum = 0.f;
        for (int s = lane; s < SS; s += 32) { float e = expf(esm[s] - m); esm[s] = e; sum += e; }
#pragma unroll
        for (int off = 16; off; off >>= 1) sum += __shfl_xor_sync(0xffffffffu, sum, off);
        if (lane == 0) red[0] = 1.f / sum;
    }
    __syncthreads();

    const float inv = red[0];
    const int d = tid * 4;
    float4 ctx = make_float4(0.f, 0.f, 0.f, 0.f);
    for (int s = 0; s < SS; s++) {
        float a = esm[s] * inv;
        float4 ev = *(const float4*)(enc + ((size_t)b * SS + s) * HH + d);
        ctx.x += a * ev.x; ctx.y += a * ev.y; ctx.z += a * ev.z; ctx.w += a * ev.w;
    }
    float* crow = comb + (size_t)bt * H2;
#pragma unroll
    for (int i = 0; i < 4; i++) crow[tid + i * 128] = ysm[tid + i * 128];
    *(float4*)(crow + HH + d) = ctx;
}

// ---------------- host launcher ----------------
static float* sym(const void* s) {
    void* p = nullptr;
    cudaGetSymbolAddress(&p, s);
    return (float*)p;
}

#define GEMM_SMEM (4 * 5120 * 4)

extern "C" void kernel_launch(void* const* d_in, const int* in_sizes, int n_in,
                              void* d_out, int out_size) {
    const int*   src_seq = (const int*)d_in[0];
    const int*   trg_seq = (const int*)d_in[1];
    const float* src_emb = (const float*)d_in[2];
    const float* trg_emb = (const float*)d_in[3];
    const float* eW0f = (const float*)d_in[4];
    const float* eU0f = (const float*)d_in[5];
    const float* eb0f = (const float*)d_in[6];
    const float* eW0b = (const float*)d_in[7];
    const float* eU0b = (const float*)d_in[8];
    const float* eb0b = (const float*)d_in[9];
    const float* eW1f = (const float*)d_in[10];
    const float* eU1f = (const float*)d_in[11];
    const float* eb1f = (const float*)d_in[12];
    const float* eW1b = (const float*)d_in[13];
    const float* eU1b = (const float*)d_in[14];
    const float* eb1b = (const float*)d_in[15];
    const float* out_W = (const float*)d_in[16];
    const float* out_b = (const float*)d_in[17];
    const float* hpW  = (const float*)d_in[18];
    const float* hpb  = (const float*)d_in[19];
    const float* cpW  = (const float*)d_in[20];
    const float* cpb  = (const float*)d_in[21];
    const float* dW0  = (const float*)d_in[22];
    const float* dU0  = (const float*)d_in[23];
    const float* db0  = (const float*)d_in[24];
    const float* dW1  = (const float*)d_in[25];
    const float* dU1  = (const float*)d_in[26];
    const float* db1  = (const float*)d_in[27];
    const float* fcW  = (const float*)d_in[28];
    const float* fcb  = (const float*)d_in[29];
    float* out = (float*)d_out;

    float* xsrc = sym(d_xsrc);
    float* ytrg = sym(d_ytrg);
    float* xpf  = sym(d_xpf);
    float* xpb  = sym(d_xpb);
    float* x1   = sym(d_x1);
    float* x2   = sym(d_x2);
    float* enc  = sym(d_enc);
    float* y1   = sym(d_y1);
    float* y2   = sym(d_y2);
    float* comb = sym(d_comb);
    float* ecT0 = sym(d_ecT0);
    float* ecT1 = sym(d_ecT1);
    float* ehT0 = sym(d_ehT0);
    float* ehT1 = sym(d_ehT1);
    float* dh0  = sym(d_dh0);
    float* dh1  = sym(d_dh1);
    float* dc0  = sym(d_dc0);
    float* dc1  = sym(d_dc1);
    float* zer  = sym(d_zeros);

    static bool attr_done = false;
    if (!attr_done) {
        cudaFuncSetAttribute(gemm_tf32, cudaFuncAttributeMaxDynamicSharedMemorySize, GEMM_SMEM);
        attr_done = true;
    }

    zero_kernel<<<(BB*HH + 255)/256, 256>>>(zer, BB*HH);
    zero_kernel<<<(BB*H2 + 255)/256, 256>>>(ecT0, BB*H2);
    zero_kernel<<<(BB*H2 + 255)/256, 256>>>(ecT1, BB*H2);

    embed_kernel<<<(BB*SS*EE + 255)/256, 256>>>(xsrc, src_emb, src_seq, BB*SS*EE);
    embed_kernel<<<(BB*TN*EE + 255)/256, 256>>>(ytrg, trg_emb, trg_seq, BB*TN*EE);

    const dim3 gXP((BB*SS)/128, H4/128);     // (24, 16) M-fast
    const dim3 gENC((BB*SS)/128, HH/128);    // (24, 4)
    const dim3 gPROJ(HH/128, 1);             // fp32 kernel layout (N-x, M-y)
    const dim3 gFC((BB*TN)/128, VV/128);     // (24, 250)

    // ===== encoder layer 0 =====
    gemm_tf32<<<gXP, 256, GEMM_SMEM>>>(xsrc, eW0f, eb0f, xpf, BB*SS, H4, EE);
    gemm_tf32<<<gXP, 256, GEMM_SMEM>>>(xsrc, eW0b, eb0b, xpb, BB*SS, H4, EE);
    for (int t = 0; t < TN; t++)
        lstm_step<<<dim3(64, 2), 256>>>(xpf, xpb, eU0f, eU0b, zer, zer,
                                        ecT0, ecT0 + 512, H2,
                                        x1, x1 + 512, H2, t, 1);

    // ===== encoder layer 1 =====
    gemm_tf32<<<gXP, 256, GEMM_SMEM>>>(x1, eW1f, eb1f, xpf, BB*SS, H4, H2);
    gemm_tf32<<<gXP, 256, GEMM_SMEM>>>(x1, eW1b, eb1b, xpb, BB*SS, H4, H2);
    for (int t = 0; t < TN; t++)
        lstm_step<<<dim3(64, 2), 256>>>(xpf, xpb, eU1f, eU1b, zer, zer,
                                        ecT1, ecT1 + 512, H2,
                                        x2, x2 + 512, H2, t, 1);

    gemm_tf32<<<gENC, 256, GEMM_SMEM>>>(x2, out_W, out_b, enc, BB*SS, HH, H2);

    gather_hT<<<(2*BB*H2 + 255)/256, 256>>>(2*BB*H2);
    sgemm_bias_nt<<<gPROJ, 256>>>(ehT0, hpW,           hpb,       dh0, BB, HH, H2);
    sgemm_bias_nt<<<gPROJ, 256>>>(ehT1, hpW + HH*H2,   hpb + HH,  dh1, BB, HH, H2);
    sgemm_bias_nt<<<gPROJ, 256>>>(ecT0, cpW,           cpb,       dc0, BB, HH, H2);
    sgemm_bias_nt<<<gPROJ, 256>>>(ecT1, cpW + HH*H2,   cpb + HH,  dc1, BB, HH, H2);

    // ===== decoder layer 0 =====
    gemm_tf32<<<gXP, 256, GEMM_SMEM>>>(ytrg, dW0, db0, xpf, BB*TN, H4, EE);
    for (int t = 0; t < TN; t++)
        lstm_step<<<dim3(64, 1), 256>>>(xpf, nullptr, dU0, nullptr, dh0, nullptr,
                                        dc0, nullptr, HH,
                                        y1, nullptr, HH, t, 0);

    // ===== decoder layer 1 =====
    gemm_tf32<<<gXP, 256, GEMM_SMEM>>>(y1, dW1, db1, xpf, BB*TN, H4, HH);
    for (int t = 0; t < TN; t++)
        lstm_step<<<dim3(64, 1), 256>>>(xpf, nullptr, dU1, nullptr, dh1, nullptr,
                                        dc1, nullptr, HH,
                                        y2, nullptr, HH, t, 0);

    // ===== attention + concat =====
    attn_kernel<<<BB*TN, 128>>>(y2, enc, src_seq, comb);

    // ===== final FC on tensor cores (TF32) =====
    gemm_tf32<<<gFC, 256, GEMM_SMEM>>>(comb, fcW, fcb, out, BB*TN, VV, H2);
}

// round 8
// speedup vs baseline: 1.3283x; 1.1968x over previous
#include <cuda_runtime.h>
#include <math.h>
#include <mma.h>
using namespace nvcuda;

#define BB 32
#define SS 96
#define TN 96
#define EE 256
#define HH 512
#define H4 2048
#define H2 1024
#define VV 32000

// ---------------- static scratch (no allocations) ----------------
__device__ float d_xsrc[BB*SS*EE];
__device__ float d_ytrg[BB*TN*EE];
__device__ float d_xpf[BB*SS*H4];
__device__ float d_xpb[BB*SS*H4];
__device__ float d_x1[BB*SS*H2];
__device__ float d_x2[BB*SS*H2];
__device__ float d_enc[BB*SS*HH];
__device__ float d_y1[BB*TN*HH];
__device__ float d_y2[BB*TN*HH];
__device__ float d_comb[BB*TN*H2];
__device__ float d_ecT0[BB*H2];
__device__ float d_ecT1[BB*H2];
__device__ float d_ehT0[BB*H2];
__device__ float d_ehT1[BB*H2];
__device__ float d_dh0[BB*HH];
__device__ float d_dh1[BB*HH];
__device__ float d_dc0[BB*HH];
__device__ float d_dc1[BB*HH];

// grid-barrier state (reset before each scan phase)
__device__ unsigned d_gcnt = 0;
__device__ unsigned d_ggen = 0;

__global__ void bar_reset_kernel() { d_gcnt = 0u; d_ggen = 0u; }

// All blocks co-resident (grid <= 148). Release via L2 atomic; poll volatile.
__device__ __forceinline__ void gbar(unsigned target) {
    __syncthreads();
    __threadfence();
    if (threadIdx.x == 0) {
        unsigned a = atomicAdd(&d_gcnt, 1u);
        if (a == gridDim.x - 1u) {
            d_gcnt = 0u;
            __threadfence();
            atomicExch(&d_ggen, target);
        } else {
            volatile unsigned* g = &d_ggen;
            while (*g < target) __nanosleep(64);
        }
    }
    __syncthreads();
}

// ---------------- helpers ----------------
__global__ void embed_kernel(float* __restrict__ out, const float* __restrict__ emb,
                             const int* __restrict__ seq, int n) {
    int i = blockIdx.x * blockDim.x + threadIdx.x;
    if (i < n) {
        int tok = seq[i >> 8];
        out[i] = emb[(size_t)tok * EE + (i & 255)];
    }
}

// ---------------- fp32 SGEMM (small projections only) ----------------
__global__ __launch_bounds__(256) void sgemm_bias_nt(
    const float* __restrict__ A, const float* __restrict__ W,
    const float* __restrict__ bias, float* __restrict__ C,
    int M, int N, int K)
{
    __shared__ float As[16][132];
    __shared__ float Ws[16][132];
    const int bm = blockIdx.y * 128;
    const int bn = blockIdx.x * 128;
    const int tid = threadIdx.x;
    const int trow = (tid >> 4) * 8;
    const int tcol = (tid & 15) * 8;

    float acc[8][8];
#pragma unroll
    for (int i = 0; i < 8; i++)
#pragma unroll
        for (int j = 0; j < 8; j++) acc[i][j] = 0.f;

    for (int k0 = 0; k0 < K; k0 += 16) {
#pragma unroll
        for (int i = 0; i < 2; i++) {
            int q = tid + i * 256;
            int r = q >> 2;
            int c = (q & 3) * 4;
            float4 v = make_float4(0.f, 0.f, 0.f, 0.f);
            if (bm + r < M) v = *(const float4*)(A + (size_t)(bm + r) * K + k0 + c);
            As[c + 0][r] = v.x; As[c + 1][r] = v.y; As[c + 2][r] = v.z; As[c + 3][r] = v.w;
            float4 u = *(const float4*)(W + (size_t)(bn + r) * K + k0 + c);
            Ws[c + 0][r] = u.x; Ws[c + 1][r] = u.y; Ws[c + 2][r] = u.z; Ws[c + 3][r] = u.w;
        }
        __syncthreads();
#pragma unroll
        for (int kk = 0; kk < 16; kk++) {
            float4 a0 = *(const float4*)&As[kk][trow];
            float4 a1 = *(const float4*)&As[kk][trow + 4];
            float4 b0 = *(const float4*)&Ws[kk][tcol];
            float4 b1 = *(const float4*)&Ws[kk][tcol + 4];
            float av[8] = {a0.x, a0.y, a0.z, a0.w, a1.x, a1.y, a1.z, a1.w};
            float bv[8] = {b0.x, b0.y, b0.z, b0.w, b1.x, b1.y, b1.z, b1.w};
#pragma unroll
            for (int i = 0; i < 8; i++)
#pragma unroll
                for (int j = 0; j < 8; j++) acc[i][j] += av[i] * bv[j];
        }
        __syncthreads();
    }

    float bb[8];
#pragma unroll
    for (int j = 0; j < 8; j++) bb[j] = bias[bn + tcol + j];
#pragma unroll
    for (int i = 0; i < 8; i++) {
        int r = bm + trow + i;
        if (r < M) {
            float* cp = C + (size_t)r * N + bn + tcol;
#pragma unroll
            for (int j = 0; j < 8; j += 4) {
                float4 v;
                v.x = acc[i][j + 0] + bb[j + 0];
                v.y = acc[i][j + 1] + bb[j + 1];
                v.z = acc[i][j + 2] + bb[j + 2];
                v.w = acc[i][j + 3] + bb[j + 3];
                *(float4*)(cp + j) = v;
            }
        }
    }
}

// ---------------- TF32 tensor-core GEMM (FC + big projections) ----------------
__global__ __launch_bounds__(256) void gemm_tf32(
    const float* __restrict__ A, const float* __restrict__ W,
    const float* __restrict__ bias, float* __restrict__ C,
    int M, int N, int K)
{
    extern __shared__ float sm[];
    float* Ab[2] = { sm,          sm + 5120 };
    float* Bb[2] = { sm + 10240,  sm + 15360 };

    const int bm = blockIdx.x * 128;
    const int bn = blockIdx.y * 128;
    const int tid  = threadIdx.x;
    const int warp = tid >> 5;
    const int lane = tid & 31;
    const int wm = warp & 3;
    const int wn = warp >> 2;

    wmma::fragment<wmma::accumulator, 16, 16, 8, float> c[2][4];
#pragma unroll
    for (int i = 0; i < 2; i++)
#pragma unroll
        for (int j = 0; j < 4; j++) wmma::fill_fragment(c[i][j], 0.f);

    const int lr = tid >> 1;
    const int lc = (tid & 1) * 16;
    const float* ap = A + (size_t)(bm + lr) * K + lc;
    const float* wp = W + (size_t)(bn + lr) * K + lc;

    float4 ra[4], rw[4];
#pragma unroll
    for (int q = 0; q < 4; q++) {
        ra[q] = *(const float4*)(ap + q * 4);
        rw[q] = *(const float4*)(wp + q * 4);
    }
    {
        float* ad = Ab[0] + lr * 40 + lc;
        float* bd = Bb[0] + lr * 40 + lc;
#pragma unroll
        for (int q = 0; q < 4; q++) {
            ad[q*4+0] = wmma::__float_to_tf32(ra[q].x);
            ad[q*4+1] = wmma::__float_to_tf32(ra[q].y);
            ad[q*4+2] = wmma::__float_to_tf32(ra[q].z);
            ad[q*4+3] = wmma::__float_to_tf32(ra[q].w);
            bd[q*4+0] = wmma::__float_to_tf32(rw[q].x);
            bd[q*4+1] = wmma::__float_to_tf32(rw[q].y);
            bd[q*4+2] = wmma::__float_to_tf32(rw[q].z);
            bd[q*4+3] = wmma::__float_to_tf32(rw[q].w);
        }
    }
    __syncthreads();

    const int ksteps = K >> 5;
    int cur = 0;
    for (int ks = 0; ks < ksteps; ks++) {
        const bool more = (ks + 1 < ksteps);
        if (more) {
            const float* a2 = ap + (ks + 1) * 32;
            const float* w2 = wp + (ks + 1) * 32;
#pragma unroll
            for (int q = 0; q < 4; q++) {
                ra[q] = *(const float4*)(a2 + q * 4);
                rw[q] = *(const float4*)(w2 + q * 4);
            }
        }
        const float* As = Ab[cur];
        const float* Bs = Bb[cur];
#pragma unroll
        for (int kk = 0; kk < 4; kk++) {
            wmma::fragment<wmma::matrix_a, 16, 16, 8, wmma::precision::tf32, wmma::row_major> a[2];
            wmma::fragment<wmma::matrix_b, 16, 16, 8, wmma::precision::tf32, wmma::col_major> b[4];
#pragma unroll
            for (int i = 0; i < 2; i++)
                wmma::load_matrix_sync(a[i], As + (wm * 32 + i * 16) * 40 + kk * 8, 40);
#pragma unroll
            for (int j = 0; j < 4; j++)
                wmma::load_matrix_sync(b[j], Bs + (wn * 64 + j * 16) * 40 + kk * 8, 40);
#pragma unroll
            for (int i = 0; i < 2; i++)
#pragma unroll
                for (int j = 0; j < 4; j++)
                    wmma::mma_sync(c[i][j], a[i], b[j], c[i][j]);
        }
        if (more) {
            float* ad = Ab[cur ^ 1] + lr * 40 + lc;
            float* bd = Bb[cur ^ 1] + lr * 40 + lc;
#pragma unroll
            for (int q = 0; q < 4; q++) {
                ad[q*4+0] = wmma::__float_to_tf32(ra[q].x);
                ad[q*4+1] = wmma::__float_to_tf32(ra[q].y);
                ad[q*4+2] = wmma::__float_to_tf32(ra[q].z);
                ad[q*4+3] = wmma::__float_to_tf32(ra[q].w);
                bd[q*4+0] = wmma::__float_to_tf32(rw[q].x);
                bd[q*4+1] = wmma::__float_to_tf32(rw[q].y);
                bd[q*4+2] = wmma::__float_to_tf32(rw[q].z);
                bd[q*4+3] = wmma::__float_to_tf32(rw[q].w);
            }
            __syncthreads();
            cur ^= 1;
        }
    }
    __syncthreads();

    float* wbuf = sm + warp * 320;
    const int er = lane >> 1;
    const int ec = (lane & 1) * 8;
#pragma unroll
    for (int i = 0; i < 2; i++) {
#pragma unroll
        for (int j = 0; j < 4; j++) {
            wmma::store_matrix_sync(wbuf, c[i][j], 20, wmma::mem_row_major);
            __syncwarp();
            const int gr = bm + wm * 32 + i * 16 + er;
            const int gc = bn + wn * 64 + j * 16 + ec;
            const float* bp = bias + gc;
            float* dst = C + (size_t)gr * N + gc;
            float4 v0, v1;
            v0.x = wbuf[er * 20 + ec + 0] + bp[0];
            v0.y = wbuf[er * 20 + ec + 1] + bp[1];
            v0.z = wbuf[er * 20 + ec + 2] + bp[2];
            v0.w = wbuf[er * 20 + ec + 3] + bp[3];
            v1.x = wbuf[er * 20 + ec + 4] + bp[4];
            v1.y = wbuf[er * 20 + ec + 5] + bp[5];
            v1.z = wbuf[er * 20 + ec + 6] + bp[6];
            v1.w = wbuf[er * 20 + ec + 7] + bp[7];
            *(float4*)(dst)     = v0;
            *(float4*)(dst + 4) = v1;
            __syncwarp();
        }
    }
}

// ---------------- persistent LSTM scan ----------------
// Each block: 8 units (j0..j0+7) x 4 gates x 32 batches. U slice resident in
// smem for all 96 steps; c in a register per thread; one grid barrier per step.
// Cross-block h via __stcg/__ldcg (L2-coherent).
#define USM_F (512*36)
#define HSM_F (2*32*36)
#define GSM_F (32*33)
#define SCAN_SMEM ((USM_F + HSM_F + GSM_F) * 4)

__device__ __forceinline__ void scan_core(
    const float* __restrict__ xp,   // [B][96][2048] for this dir
    const float* __restrict__ U,    // [2048][512]
    const float* __restrict__ h0,   // [B][512] initial h (null => zeros)
    const float* __restrict__ c0,   // [B][512] initial c (null => zeros)
    float* __restrict__ hs,         // out: (b*96+t)*ostr + j (dir offset pre-added)
    float* __restrict__ cT,         // final c out (stride H2), may be null
    int ostr, int rev, int j0, float* sm)
{
    float* usm = sm;                        // [k*36 + r]
    float* hsm = sm + USM_F;                // [buf*1152 + k*36 + b]
    float* gsm = sm + USM_F + HSM_F;        // [r*33 + b]

    const int tid = threadIdx.x;

    // load U slice (32 gate-rows x 512) transposed into smem, once
    {
        const int ulr = tid >> 3;
        const int ulk = (tid & 7) * 4;
        const int grow = ((ulr >> 3) * HH) + j0 + (ulr & 7);
        const float* ub = U + (size_t)grow * HH;
        for (int kb = 0; kb < HH; kb += 32) {
            float4 u = *(const float4*)(ub + kb + ulk);
            usm[(kb+ulk+0)*36 + ulr] = u.x;
            usm[(kb+ulk+1)*36 + ulr] = u.y;
            usm[(kb+ulk+2)*36 + ulr] = u.z;
            usm[(kb+ulk+3)*36 + ulr] = u.w;
        }
    }

    const int rr  = tid >> 3;          // gate-row 0..31
    const int b0t = (tid & 7) * 4;     // batch group for compute
    const int lb  = tid >> 3;          // batch for h loads
    const int lkk = (tid & 7) * 4;     // k offset for h loads
    const int pu  = tid >> 5;          // pointwise unit 0..7
    const int pb  = tid & 31;          // pointwise batch

    float creg = c0 ? c0[(size_t)pb * HH + j0 + pu] : 0.f;
    __syncthreads();

    for (int t = 0; t < TN; t++) {
        const int tt = rev ? (TN - 1 - t) : t;
        float acc0 = 0.f, acc1 = 0.f, acc2 = 0.f, acc3 = 0.f;

        const float* hb = nullptr;
        size_t hstr = 0;
        if (t == 0) {
            if (h0) { hb = h0; hstr = HH; }
        } else {
            const int tprev = rev ? (tt + 1) : (tt - 1);
            hb = hs + (size_t)tprev * ostr;
            hstr = (size_t)TN * ostr;
        }

        if (hb) {
            const float* hrow = hb + (size_t)lb * hstr;
            float4 pre = __ldcg((const float4*)(hrow + lkk));
            for (int k0 = 0; k0 < HH; k0 += 32) {
                float* hbuf = hsm + ((k0 >> 5) & 1) * (32 * 36);
                hbuf[(lkk+0)*36 + lb] = pre.x;
                hbuf[(lkk+1)*36 + lb] = pre.y;
                hbuf[(lkk+2)*36 + lb] = pre.z;
                hbuf[(lkk+3)*36 + lb] = pre.w;
                if (k0 + 32 < HH)
                    pre = __ldcg((const float4*)(hrow + k0 + 32 + lkk));
                __syncthreads();
                const float* urow = usm + (size_t)k0 * 36 + rr;
#pragma unroll
                for (int kk = 0; kk < 32; kk++) {
                    float uu = urow[kk * 36];
                    float4 hv = *(const float4*)(hbuf + kk * 36 + b0t);
                    acc0 += uu * hv.x; acc1 += uu * hv.y;
                    acc2 += uu * hv.z; acc3 += uu * hv.w;
                }
            }
            __syncthreads();   // hsm/gsm region reuse + gsm WAR from prev step
        }

        gsm[rr*33 + b0t + 0] = acc0;
        gsm[rr*33 + b0t + 1] = acc1;
        gsm[rr*33 + b0t + 2] = acc2;
        gsm[rr*33 + b0t + 3] = acc3;
        __syncthreads();

        {
            const size_t xb = ((size_t)pb * TN + tt) * H4 + j0 + pu;
            float gi = gsm[pu*33 + pb]        + xp[xb];
            float gf = gsm[(8 + pu)*33 + pb]  + xp[xb + 512];
            float gg = gsm[(16 + pu)*33 + pb] + xp[xb + 1024];
            float go = gsm[(24 + pu)*33 + pb] + xp[xb + 1536];
            float si = 1.f / (1.f + expf(-gi));
            float sf = 1.f / (1.f + expf(-gf));
            float so = 1.f / (1.f + expf(-go));
            float tg = tanhf(gg);
            creg = sf * creg + si * tg;
            __stcg(hs + ((size_t)pb * TN + tt) * ostr + j0 + pu, so * tanhf(creg));
        }

        if (t + 1 < TN) gbar((unsigned)(t + 1));
    }

    if (cT) cT[(size_t)pb * H2 + j0 + pu] = creg;
}

__global__ __launch_bounds__(256) void lstm_scan_enc(
    const float* __restrict__ xpf, const float* __restrict__ xpb,
    const float* __restrict__ Uf,  const float* __restrict__ Ub,
    float* __restrict__ hs, float* __restrict__ cT)
{
    extern __shared__ float sm[];
    const int dir = blockIdx.x >> 6;
    const int j0  = (blockIdx.x & 63) * 8;
    scan_core(dir ? xpb : xpf, dir ? Ub : Uf, nullptr, nullptr,
              hs + dir * 512, cT + dir * 512, H2, dir, j0, sm);
}

__global__ __launch_bounds__(256) void lstm_scan_dec(
    const float* __restrict__ xp, const float* __restrict__ U,
    const float* __restrict__ h0, const float* __restrict__ c0,
    float* __restrict__ hs)
{
    extern __shared__ float sm[];
    const int j0 = blockIdx.x * 8;
    scan_core(xp, U, h0, c0, hs, nullptr, HH, 0, j0, sm);
}

__global__ void gather_hT(int n) {
    int i = blockIdx.x * blockDim.x + threadIdx.x;
    if (i >= n) return;
    int l = i >> 15;
    int r = i & 32767;
    int b = r >> 10;
    int j = r & 1023;
    const float* src = l ? d_x2 : d_x1;
    int tt = (j < 512) ? (SS - 1) : 0;
    float v = src[((size_t)b * SS + tt) * H2 + j];
    (l ? d_ehT1 : d_ehT0)[b * H2 + j] = v;
}

// ---------------- attention + concat ----------------
__global__ __launch_bounds__(128) void attn_kernel(
    const float* __restrict__ y, const float* __restrict__ enc,
    const int* __restrict__ src_seq, float* __restrict__ comb)
{
    const int bt = blockIdx.x;
    const int b = bt / TN;
    __shared__ float ysm[HH];
    __shared__ float esm[SS];
    __shared__ float red[1];
    const int tid = threadIdx.x;
    const float* yrow = y + (size_t)bt * HH;
#pragma unroll
    for (int i = 0; i < 4; i++) ysm[tid + i * 128] = yrow[tid + i * 128];
    __syncthreads();

    const int lane = tid & 31, w = tid >> 5;
    for (int s = w; s < SS; s += 4) {
        const float* er = enc + ((size_t)b * SS + s) * HH;
        float p = 0.f;
        for (int d = lane; d < HH; d += 32) p += ysm[d] * er[d];
#pragma unroll
        for (int off = 16; off; off >>= 1) p += __shfl_xor_sync(0xffffffffu, p, off);
        if (lane == 0) esm[s] = (src_seq[b * SS + s] != 0) ? p : -1e10f;
    }
    __syncthreads();

    if (w == 0) {
        float m = -1e30f;
        for (int s = lane; s < SS; s += 32) m = fmaxf(m, esm[s]);
#pragma unroll
        for (int off = 16; off; off >>= 1) m = fmaxf(m, __shfl_xor_sync(0xffffffffu, m, off));
        float sum = 0.f;
        for (int s = lane; s < SS; s += 32) { float e = expf(esm[s] - m); esm[s] = e; sum += e; }
#pragma unroll
        for (int off = 16; off; off >>= 1) sum += __shfl_xor_sync(0xffffffffu, sum, off);
        if (lane == 0) red[0] = 1.f / sum;
    }
    __syncthreads();

    const float inv = red[0];
    const int d = tid * 4;
    float4 ctx = make_float4(0.f, 0.f, 0.f, 0.f);
    for (int s = 0; s < SS; s++) {
        float a = esm[s] * inv;
        float4 ev = *(const float4*)(enc + ((size_t)b * SS + s) * HH + d);
        ctx.x += a * ev.x; ctx.y += a * ev.y; ctx.z += a * ev.z; ctx.w += a * ev.w;
    }
    float* crow = comb + (size_t)bt * H2;
#pragma unroll
    for (int i = 0; i < 4; i++) crow[tid + i * 128] = ysm[tid + i * 128];
    *(float4*)(crow + HH + d) = ctx;
}

// ---------------- host launcher ----------------
static float* sym(const void* s) {
    void* p = nullptr;
    cudaGetSymbolAddress(&p, s);
    return (float*)p;
}

#define GEMM_SMEM (4 * 5120 * 4)

extern "C" void kernel_launch(void* const* d_in, const int* in_sizes, int n_in,
                              void* d_out, int out_size) {
    const int*   src_seq = (const int*)d_in[0];
    const int*   trg_seq = (const int*)d_in[1];
    const float* src_emb = (const float*)d_in[2];
    const float* trg_emb = (const float*)d_in[3];
    const float* eW0f = (const float*)d_in[4];
    const float* eU0f = (const float*)d_in[5];
    const float* eb0f = (const float*)d_in[6];
    const float* eW0b = (const float*)d_in[7];
    const float* eU0b = (const float*)d_in[8];
    const float* eb0b = (const float*)d_in[9];
    const float* eW1f = (const float*)d_in[10];
    const float* eU1f = (const float*)d_in[11];
    const float* eb1f = (const float*)d_in[12];
    const float* eW1b = (const float*)d_in[13];
    const float* eU1b = (const float*)d_in[14];
    const float* eb1b = (const float*)d_in[15];
    const float* out_W = (const float*)d_in[16];
    const float* out_b = (const float*)d_in[17];
    const float* hpW  = (const float*)d_in[18];
    const float* hpb  = (const float*)d_in[19];
    const float* cpW  = (const float*)d_in[20];
    const float* cpb  = (const float*)d_in[21];
    const float* dW0  = (const float*)d_in[22];
    const float* dU0  = (const float*)d_in[23];
    const float* db0  = (const float*)d_in[24];
    const float* dW1  = (const float*)d_in[25];
    const float* dU1  = (const float*)d_in[26];
    const float* db1  = (const float*)d_in[27];
    const float* fcW  = (const float*)d_in[28];
    const float* fcb  = (const float*)d_in[29];
    float* out = (float*)d_out;

    float* xsrc = sym(d_xsrc);
    float* ytrg = sym(d_ytrg);
    float* xpf  = sym(d_xpf);
    float* xpb  = sym(d_xpb);
    float* x1   = sym(d_x1);
    float* x2   = sym(d_x2);
    float* enc  = sym(d_enc);
    float* y1   = sym(d_y1);
    float* y2   = sym(d_y2);
    float* comb = sym(d_comb);
    float* ecT0 = sym(d_ecT0);
    float* ecT1 = sym(d_ecT1);
    float* ehT0 = sym(d_ehT0);
    float* ehT1 = sym(d_ehT1);
    float* dh0  = sym(d_dh0);
    float* dh1  = sym(d_dh1);
    float* dc0  = sym(d_dc0);
    float* dc1  = sym(d_dc1);

    static bool attr_done = false;
    if (!attr_done) {
        cudaFuncSetAttribute(gemm_tf32, cudaFuncAttributeMaxDynamicSharedMemorySize, GEMM_SMEM);
        cudaFuncSetAttribute(lstm_scan_enc, cudaFuncAttributeMaxDynamicSharedMemorySize, SCAN_SMEM);
        cudaFuncSetAttribute(lstm_scan_dec, cudaFuncAttributeMaxDynamicSharedMemorySize, SCAN_SMEM);
        attr_done = true;
    }

    embed_kernel<<<(BB*SS*EE + 255)/256, 256>>>(xsrc, src_emb, src_seq, BB*SS*EE);
    embed_kernel<<<(BB*TN*EE + 255)/256, 256>>>(ytrg, trg_emb, trg_seq, BB*TN*EE);

    const dim3 gXP((BB*SS)/128, H4/128);     // (24, 16) M-fast
    const dim3 gENC((BB*SS)/128, HH/128);    // (24, 4)
    const dim3 gPROJ(HH/128, 1);             // fp32 kernel layout (N-x, M-y)
    const dim3 gFC((BB*TN)/128, VV/128);     // (24, 250)

    // ===== encoder layer 0 =====
    gemm_tf32<<<gXP, 256, GEMM_SMEM>>>(xsrc, eW0f, eb0f, xpf, BB*SS, H4, EE);
    gemm_tf32<<<gXP, 256, GEMM_SMEM>>>(xsrc, eW0b, eb0b, xpb, BB*SS, H4, EE);
    bar_reset_kernel<<<1, 1>>>();
    lstm_scan_enc<<<128, 256, SCAN_SMEM>>>(xpf, xpb, eU0f, eU0b, x1, ecT0);

    // ===== encoder layer 1 =====
    gemm_tf32<<<gXP, 256, GEMM_SMEM>>>(x1, eW1f, eb1f, xpf, BB*SS, H4, H2);
    gemm_tf32<<<gXP, 256, GEMM_SMEM>>>(x1, eW1b, eb1b, xpb, BB*SS, H4, H2);
    bar_reset_kernel<<<1, 1>>>();
    lstm_scan_enc<<<128, 256, SCAN_SMEM>>>(xpf, xpb, eU1f, eU1b, x2, ecT1);

    gemm_tf32<<<gENC, 256, GEMM_SMEM>>>(x2, out_W, out_b, enc, BB*SS, HH, H2);

    gather_hT<<<(2*BB*H2 + 255)/256, 256>>>(2*BB*H2);
    sgemm_bias_nt<<<gPROJ, 256>>>(ehT0, hpW,           hpb,       dh0, BB, HH, H2);
    sgemm_bias_nt<<<gPROJ, 256>>>(ehT1, hpW + HH*H2,   hpb + HH,  dh1, BB, HH, H2);
    sgemm_bias_nt<<<gPROJ, 256>>>(ecT0, cpW,           cpb,       dc0, BB, HH, H2);
    sgemm_bias_nt<<<gPROJ, 256>>>(ecT1, cpW + HH*H2,   cpb + HH,  dc1, BB, HH, H2);

    // ===== decoder layer 0 =====
    gemm_tf32<<<gXP, 256, GEMM_SMEM>>>(ytrg, dW0, db0, xpf, BB*TN, H4, EE);
    bar_reset_kernel<<<1, 1>>>();
    lstm_scan_dec<<<64, 256, SCAN_SMEM>>>(xpf, dU0, dh0, dc0, y1);

    // ===== decoder layer 1 =====
    gemm_tf32<<<gXP, 256, GEMM_SMEM>>>(y1, dW1, db1, xpf, BB*TN, H4, HH);
    bar_reset_kernel<<<1, 1>>>();
    lstm_scan_dec<<<64, 256, SCAN_SMEM>>>(xpf, dU1, dh1, dc1, y2);

    // ===== attention + concat =====
    attn_kernel<<<BB*TN, 128>>>(y2, enc, src_seq, comb);

    // ===== final FC on tensor cores (TF32) =====
    gemm_tf32<<<gFC, 256, GEMM_SMEM>>>(comb, fcW, fcb, out, BB*TN, VV, H2);
}

// round 9
// speedup vs baseline: 1.3795x; 1.0385x over previous
#include <cuda_runtime.h>
#include <math.h>
#include <mma.h>
using namespace nvcuda;

#define BB 32
#define SS 96
#define TN 96
#define EE 256
#define HH 512
#define H4 2048
#define H2 1024
#define VV 32000

// ---------------- static scratch (no allocations) ----------------
__device__ float d_xsrc[BB*SS*EE];
__device__ float d_ytrg[BB*TN*EE];
__device__ float d_xpf[BB*SS*H4];
__device__ float d_xpb[BB*SS*H4];
__device__ float d_x1[BB*SS*H2];
__device__ float d_x2[BB*SS*H2];
__device__ float d_enc[BB*SS*HH];
__device__ float d_y1[BB*TN*HH];
__device__ float d_y2[BB*TN*HH];
__device__ float d_comb[BB*TN*H2];
__device__ float d_ecT0[BB*H2];
__device__ float d_ecT1[BB*H2];
__device__ float d_ehT0[BB*H2];
__device__ float d_ehT1[BB*H2];
__device__ float d_dh0[BB*HH];
__device__ float d_dh1[BB*HH];
__device__ float d_dc0[BB*HH];
__device__ float d_dc1[BB*HH];

// per-block step flags (distributed barrier); [dir*64 + jblk]
__device__ unsigned d_flag[128];

__global__ void flag_reset_kernel() {
    if (threadIdx.x < 128) d_flag[threadIdx.x] = 0u;
}

// ---------------- helpers ----------------
__global__ void embed_kernel(float* __restrict__ out, const float* __restrict__ emb,
                             const int* __restrict__ seq, int n) {
    int i = blockIdx.x * blockDim.x + threadIdx.x;
    if (i < n) {
        int tok = seq[i >> 8];
        out[i] = emb[(size_t)tok * EE + (i & 255)];
    }
}

// ---------------- fp32 SGEMM (small projections only) ----------------
__global__ __launch_bounds__(256) void sgemm_bias_nt(
    const float* __restrict__ A, const float* __restrict__ W,
    const float* __restrict__ bias, float* __restrict__ C,
    int M, int N, int K)
{
    __shared__ float As[16][132];
    __shared__ float Ws[16][132];
    const int bm = blockIdx.y * 128;
    const int bn = blockIdx.x * 128;
    const int tid = threadIdx.x;
    const int trow = (tid >> 4) * 8;
    const int tcol = (tid & 15) * 8;

    float acc[8][8];
#pragma unroll
    for (int i = 0; i < 8; i++)
#pragma unroll
        for (int j = 0; j < 8; j++) acc[i][j] = 0.f;

    for (int k0 = 0; k0 < K; k0 += 16) {
#pragma unroll
        for (int i = 0; i < 2; i++) {
            int q = tid + i * 256;
            int r = q >> 2;
            int c = (q & 3) * 4;
            float4 v = make_float4(0.f, 0.f, 0.f, 0.f);
            if (bm + r < M) v = *(const float4*)(A + (size_t)(bm + r) * K + k0 + c);
            As[c + 0][r] = v.x; As[c + 1][r] = v.y; As[c + 2][r] = v.z; As[c + 3][r] = v.w;
            float4 u = *(const float4*)(W + (size_t)(bn + r) * K + k0 + c);
            Ws[c + 0][r] = u.x; Ws[c + 1][r] = u.y; Ws[c + 2][r] = u.z; Ws[c + 3][r] = u.w;
        }
        __syncthreads();
#pragma unroll
        for (int kk = 0; kk < 16; kk++) {
            float4 a0 = *(const float4*)&As[kk][trow];
            float4 a1 = *(const float4*)&As[kk][trow + 4];
            float4 b0 = *(const float4*)&Ws[kk][tcol];
            float4 b1 = *(const float4*)&Ws[kk][tcol + 4];
            float av[8] = {a0.x, a0.y, a0.z, a0.w, a1.x, a1.y, a1.z, a1.w};
            float bv[8] = {b0.x, b0.y, b0.z, b0.w, b1.x, b1.y, b1.z, b1.w};
#pragma unroll
            for (int i = 0; i < 8; i++)
#pragma unroll
                for (int j = 0; j < 8; j++) acc[i][j] += av[i] * bv[j];
        }
        __syncthreads();
    }

    float bb[8];
#pragma unroll
    for (int j = 0; j < 8; j++) bb[j] = bias[bn + tcol + j];
#pragma unroll
    for (int i = 0; i < 8; i++) {
        int r = bm + trow + i;
        if (r < M) {
            float* cp = C + (size_t)r * N + bn + tcol;
#pragma unroll
            for (int j = 0; j < 8; j += 4) {
                float4 v;
                v.x = acc[i][j + 0] + bb[j + 0];
                v.y = acc[i][j + 1] + bb[j + 1];
                v.z = acc[i][j + 2] + bb[j + 2];
                v.w = acc[i][j + 3] + bb[j + 3];
                *(float4*)(cp + j) = v;
            }
        }
    }
}

// ---------------- TF32 tensor-core GEMM (FC + big projections) ----------------
__global__ __launch_bounds__(256) void gemm_tf32(
    const float* __restrict__ A, const float* __restrict__ W,
    const float* __restrict__ bias, float* __restrict__ C,
    int M, int N, int K)
{
    extern __shared__ float sm[];
    float* Ab[2] = { sm,          sm + 5120 };
    float* Bb[2] = { sm + 10240,  sm + 15360 };

    const int bm = blockIdx.x * 128;
    const int bn = blockIdx.y * 128;
    const int tid  = threadIdx.x;
    const int warp = tid >> 5;
    const int lane = tid & 31;
    const int wm = warp & 3;
    const int wn = warp >> 2;

    wmma::fragment<wmma::accumulator, 16, 16, 8, float> c[2][4];
#pragma unroll
    for (int i = 0; i < 2; i++)
#pragma unroll
        for (int j = 0; j < 4; j++) wmma::fill_fragment(c[i][j], 0.f);

    const int lr = tid >> 1;
    const int lc = (tid & 1) * 16;
    const float* ap = A + (size_t)(bm + lr) * K + lc;
    const float* wp = W + (size_t)(bn + lr) * K + lc;

    float4 ra[4], rw[4];
#pragma unroll
    for (int q = 0; q < 4; q++) {
        ra[q] = *(const float4*)(ap + q * 4);
        rw[q] = *(const float4*)(wp + q * 4);
    }
    {
        float* ad = Ab[0] + lr * 40 + lc;
        float* bd = Bb[0] + lr * 40 + lc;
#pragma unroll
        for (int q = 0; q < 4; q++) {
            ad[q*4+0] = wmma::__float_to_tf32(ra[q].x);
            ad[q*4+1] = wmma::__float_to_tf32(ra[q].y);
            ad[q*4+2] = wmma::__float_to_tf32(ra[q].z);
            ad[q*4+3] = wmma::__float_to_tf32(ra[q].w);
            bd[q*4+0] = wmma::__float_to_tf32(rw[q].x);
            bd[q*4+1] = wmma::__float_to_tf32(rw[q].y);
            bd[q*4+2] = wmma::__float_to_tf32(rw[q].z);
            bd[q*4+3] = wmma::__float_to_tf32(rw[q].w);
        }
    }
    __syncthreads();

    const int ksteps = K >> 5;
    int cur = 0;
    for (int ks = 0; ks < ksteps; ks++) {
        const bool more = (ks + 1 < ksteps);
        if (more) {
            const float* a2 = ap + (ks + 1) * 32;
            const float* w2 = wp + (ks + 1) * 32;
#pragma unroll
            for (int q = 0; q < 4; q++) {
                ra[q] = *(const float4*)(a2 + q * 4);
                rw[q] = *(const float4*)(w2 + q * 4);
            }
        }
        const float* As = Ab[cur];
        const float* Bs = Bb[cur];
#pragma unroll
        for (int kk = 0; kk < 4; kk++) {
            wmma::fragment<wmma::matrix_a, 16, 16, 8, wmma::precision::tf32, wmma::row_major> a[2];
            wmma::fragment<wmma::matrix_b, 16, 16, 8, wmma::precision::tf32, wmma::col_major> b[4];
#pragma unroll
            for (int i = 0; i < 2; i++)
                wmma::load_matrix_sync(a[i], As + (wm * 32 + i * 16) * 40 + kk * 8, 40);
#pragma unroll
            for (int j = 0; j < 4; j++)
                wmma::load_matrix_sync(b[j], Bs + (wn * 64 + j * 16) * 40 + kk * 8, 40);
#pragma unroll
            for (int i = 0; i < 2; i++)
#pragma unroll
                for (int j = 0; j < 4; j++)
                    wmma::mma_sync(c[i][j], a[i], b[j], c[i][j]);
        }
        if (more) {
            float* ad = Ab[cur ^ 1] + lr * 40 + lc;
            float* bd = Bb[cur ^ 1] + lr * 40 + lc;
#pragma unroll
            for (int q = 0; q < 4; q++) {
                ad[q*4+0] = wmma::__float_to_tf32(ra[q].x);
                ad[q*4+1] = wmma::__float_to_tf32(ra[q].y);
                ad[q*4+2] = wmma::__float_to_tf32(ra[q].z);
                ad[q*4+3] = wmma::__float_to_tf32(ra[q].w);
                bd[q*4+0] = wmma::__float_to_tf32(rw[q].x);
                bd[q*4+1] = wmma::__float_to_tf32(rw[q].y);
                bd[q*4+2] = wmma::__float_to_tf32(rw[q].z);
                bd[q*4+3] = wmma::__float_to_tf32(rw[q].w);
            }
            __syncthreads();
            cur ^= 1;
        }
    }
    __syncthreads();

    float* wbuf = sm + warp * 320;
    const int er = lane >> 1;
    const int ec = (lane & 1) * 8;
#pragma unroll
    for (int i = 0; i < 2; i++) {
#pragma unroll
        for (int j = 0; j < 4; j++) {
            wmma::store_matrix_sync(wbuf, c[i][j], 20, wmma::mem_row_major);
            __syncwarp();
            const int gr = bm + wm * 32 + i * 16 + er;
            const int gc = bn + wn * 64 + j * 16 + ec;
            const float* bp = bias + gc;
            float* dst = C + (size_t)gr * N + gc;
            float4 v0, v1;
            v0.x = wbuf[er * 20 + ec + 0] + bp[0];
            v0.y = wbuf[er * 20 + ec + 1] + bp[1];
            v0.z = wbuf[er * 20 + ec + 2] + bp[2];
            v0.w = wbuf[er * 20 + ec + 3] + bp[3];
            v1.x = wbuf[er * 20 + ec + 4] + bp[4];
            v1.y = wbuf[er * 20 + ec + 5] + bp[5];
            v1.z = wbuf[er * 20 + ec + 6] + bp[6];
            v1.w = wbuf[er * 20 + ec + 7] + bp[7];
            *(float4*)(dst)     = v0;
            *(float4*)(dst + 4) = v1;
            __syncwarp();
        }
    }
}

// ---------------- persistent LSTM scan (distributed flag barrier) ----------------
// Each block: 8 units (j0..j0+7) x 4 gates x 32 batches. U slice resident in
// smem; c in a register; per-step sync via per-block flags (no central barrier).
#define USM_F (512*36)
#define HSM_F (2*32*36)
#define GSM_F (32*33)
#define SCAN_SMEM ((USM_F + HSM_F + GSM_F) * 4)

__device__ __forceinline__ void scan_core(
    const float* __restrict__ xp,   // [B][96][2048] for this dir
    const float* __restrict__ U,    // [2048][512]
    const float* __restrict__ h0,   // [B][512] initial h (null => zeros)
    const float* __restrict__ c0,   // [B][512] initial c (null => zeros)
    float* __restrict__ hs,         // out: (b*96+t)*ostr + j (dir offset pre-added)
    float* __restrict__ cT,         // final c out (stride H2), may be null
    unsigned* __restrict__ flags,   // 64 flags for this dir group
    int myblk,
    int ostr, int rev, int j0, float* sm)
{
    float* usm = sm;                        // [k*36 + r]
    float* hsm = sm + USM_F;                // [buf*1152 + k*36 + b]
    float* gsm = sm + USM_F + HSM_F;        // [r*33 + b]

    const int tid = threadIdx.x;

    // load U slice (32 gate-rows x 512) transposed into smem, once
    {
        const int ulr = tid >> 3;
        const int ulk = (tid & 7) * 4;
        const int grow = ((ulr >> 3) * HH) + j0 + (ulr & 7);
        const float* ub = U + (size_t)grow * HH;
        for (int kb = 0; kb < HH; kb += 32) {
            float4 u = *(const float4*)(ub + kb + ulk);
            usm[(kb+ulk+0)*36 + ulr] = u.x;
            usm[(kb+ulk+1)*36 + ulr] = u.y;
            usm[(kb+ulk+2)*36 + ulr] = u.z;
            usm[(kb+ulk+3)*36 + ulr] = u.w;
        }
    }

    const int rr  = tid >> 3;          // gate-row 0..31
    const int b0t = (tid & 7) * 4;     // batch group for compute
    const int lb  = tid >> 3;          // batch for h loads
    const int lkk = (tid & 7) * 4;     // k offset for h loads
    const int pu  = tid >> 5;          // pointwise unit 0..7
    const int pb  = tid & 31;          // pointwise batch

    float creg = c0 ? c0[(size_t)pb * HH + j0 + pu] : 0.f;
    volatile unsigned* myflag = (tid < 64) ? (flags + tid) : nullptr;
    __syncthreads();

    for (int t = 0; t < TN; t++) {
        const int tt = rev ? (TN - 1 - t) : t;

        // prefetch the xp gate operands for this step (consumed after the gemv)
        const size_t xb = ((size_t)pb * TN + tt) * H4 + j0 + pu;
        const float xgi = xp[xb];
        const float xgf = xp[xb + 512];
        const float xgg = xp[xb + 1024];
        const float xgo = xp[xb + 1536];

        float acc0 = 0.f, acc1 = 0.f, acc2 = 0.f, acc3 = 0.f;

        const float* hb = nullptr;
        size_t hstr = 0;
        if (t == 0) {
            if (h0) { hb = h0; hstr = HH; }
        } else {
            const int tprev = rev ? (tt + 1) : (tt - 1);
            hb = hs + (size_t)tprev * ostr;
            hstr = (size_t)TN * ostr;
        }

        if (hb) {
            if (t > 0) {
                // distributed wait: 64 threads each spin on one producer flag
                if (myflag) { while (*myflag < (unsigned)t) { } }
                __syncthreads();
            }
            const float* hrow = hb + (size_t)lb * hstr;
            float4 pre = __ldcg((const float4*)(hrow + lkk));
            for (int k0 = 0; k0 < HH; k0 += 32) {
                float* hbuf = hsm + ((k0 >> 5) & 1) * (32 * 36);
                hbuf[(lkk+0)*36 + lb] = pre.x;
                hbuf[(lkk+1)*36 + lb] = pre.y;
                hbuf[(lkk+2)*36 + lb] = pre.z;
                hbuf[(lkk+3)*36 + lb] = pre.w;
                if (k0 + 32 < HH)
                    pre = __ldcg((const float4*)(hrow + k0 + 32 + lkk));
                __syncthreads();
                const float* urow = usm + (size_t)k0 * 36 + rr;
#pragma unroll
                for (int kk = 0; kk < 32; kk++) {
                    float uu = urow[kk * 36];
                    float4 hv = *(const float4*)(hbuf + kk * 36 + b0t);
                    acc0 += uu * hv.x; acc1 += uu * hv.y;
                    acc2 += uu * hv.z; acc3 += uu * hv.w;
                }
            }
            __syncthreads();   // hsm reuse + gsm WAR from prev step
        }

        gsm[rr*33 + b0t + 0] = acc0;
        gsm[rr*33 + b0t + 1] = acc1;
        gsm[rr*33 + b0t + 2] = acc2;
        gsm[rr*33 + b0t + 3] = acc3;
        __syncthreads();

        {
            float gi = gsm[pu*33 + pb]        + xgi;
            float gf = gsm[(8 + pu)*33 + pb]  + xgf;
            float gg = gsm[(16 + pu)*33 + pb] + xgg;
            float go = gsm[(24 + pu)*33 + pb] + xgo;
            float si = 1.f / (1.f + expf(-gi));
            float sf = 1.f / (1.f + expf(-gf));
            float so = 1.f / (1.f + expf(-go));
            float tg = tanhf(gg);
            creg = sf * creg + si * tg;
            __stcg(hs + ((size_t)pb * TN + tt) * ostr + j0 + pu, so * tanhf(creg));
        }
        __syncthreads();
        if (tid == 0) {
            __threadfence();                       // publish this block's h stores
            atomicExch(&flags[myblk], (unsigned)(t + 1));
        }
        // no step-end wait: consumers gate themselves at the next step start
    }

    if (cT) cT[(size_t)pb * H2 + j0 + pu] = creg;
}

__global__ __launch_bounds__(256) void lstm_scan_enc(
    const float* __restrict__ xpf, const float* __restrict__ xpb,
    const float* __restrict__ Uf,  const float* __restrict__ Ub,
    float* __restrict__ hs, float* __restrict__ cT)
{
    extern __shared__ float sm[];
    const int dir = blockIdx.x >> 6;
    const int jb  = blockIdx.x & 63;
    scan_core(dir ? xpb : xpf, dir ? Ub : Uf, nullptr, nullptr,
              hs + dir * 512, cT + dir * 512,
              d_flag + dir * 64, jb, H2, dir, jb * 8, sm);
}

__global__ __launch_bounds__(256) void lstm_scan_dec(
    const float* __restrict__ xp, const float* __restrict__ U,
    const float* __restrict__ h0, const float* __restrict__ c0,
    float* __restrict__ hs)
{
    extern __shared__ float sm[];
    const int jb = blockIdx.x;
    scan_core(xp, U, h0, c0, hs, nullptr, d_flag, jb, HH, 0, jb * 8, sm);
}

__global__ void gather_hT(int n) {
    int i = blockIdx.x * blockDim.x + threadIdx.x;
    if (i >= n) return;
    int l = i >> 15;
    int r = i & 32767;
    int b = r >> 10;
    int j = r & 1023;
    const float* src = l ? d_x2 : d_x1;
    int tt = (j < 512) ? (SS - 1) : 0;
    float v = src[((size_t)b * SS + tt) * H2 + j];
    (l ? d_ehT1 : d_ehT0)[b * H2 + j] = v;
}

// ---------------- attention + concat ----------------
__global__ __launch_bounds__(128) void attn_kernel(
    const float* __restrict__ y, const float* __restrict__ enc,
    const int* __restrict__ src_seq, float* __restrict__ comb)
{
    const int bt = blockIdx.x;
    const int b = bt / TN;
    __shared__ float ysm[HH];
    __shared__ float esm[SS];
    __shared__ float red[1];
    const int tid = threadIdx.x;
    const float* yrow = y + (size_t)bt * HH;
#pragma unroll
    for (int i = 0; i < 4; i++) ysm[tid + i * 128] = yrow[tid + i * 128];
    __syncthreads();

    const int lane = tid & 31, w = tid >> 5;
    for (int s = w; s < SS; s += 4) {
        const float* er = enc + ((size_t)b * SS + s) * HH;
        float p = 0.f;
        for (int d = lane; d < HH; d += 32) p += ysm[d] * er[d];
#pragma unroll
        for (int off = 16; off; off >>= 1) p += __shfl_xor_sync(0xffffffffu, p, off);
        if (lane == 0) esm[s] = (src_seq[b * SS + s] != 0) ? p : -1e10f;
    }
    __syncthreads();

    if (w == 0) {
        float m = -1e30f;
        for (int s = lane; s < SS; s += 32) m = fmaxf(m, esm[s]);
#pragma unroll
        for (int off = 16; off; off >>= 1) m = fmaxf(m, __shfl_xor_sync(0xffffffffu, m, off));
        float sum = 0.f;
        for (int s = lane; s < SS; s += 32) { float e = expf(esm[s] - m); esm[s] = e; sum += e; }
#pragma unroll
        for (int off = 16; off; off >>= 1) sum += __shfl_xor_sync(0xffffffffu, sum, off);
        if (lane == 0) red[0] = 1.f / sum;
    }
    __syncthreads();

    const float inv = red[0];
    const int d = tid * 4;
    float4 ctx = make_float4(0.f, 0.f, 0.f, 0.f);
    for (int s = 0; s < SS; s++) {
        float a = esm[s] * inv;
        float4 ev = *(const float4*)(enc + ((size_t)b * SS + s) * HH + d);
        ctx.x += a * ev.x; ctx.y += a * ev.y; ctx.z += a * ev.z; ctx.w += a * ev.w;
    }
    float* crow = comb + (size_t)bt * H2;
#pragma unroll
    for (int i = 0; i < 4; i++) crow[tid + i * 128] = ysm[tid + i * 128];
    *(float4*)(crow + HH + d) = ctx;
}

// ---------------- host launcher ----------------
static float* sym(const void* s) {
    void* p = nullptr;
    cudaGetSymbolAddress(&p, s);
    return (float*)p;
}

#define GEMM_SMEM (4 * 5120 * 4)

extern "C" void kernel_launch(void* const* d_in, const int* in_sizes, int n_in,
                              void* d_out, int out_size) {
    const int*   src_seq = (const int*)d_in[0];
    const int*   trg_seq = (const int*)d_in[1];
    const float* src_emb = (const float*)d_in[2];
    const float* trg_emb = (const float*)d_in[3];
    const float* eW0f = (const float*)d_in[4];
    const float* eU0f = (const float*)d_in[5];
    const float* eb0f = (const float*)d_in[6];
    const float* eW0b = (const float*)d_in[7];
    const float* eU0b = (const float*)d_in[8];
    const float* eb0b = (const float*)d_in[9];
    const float* eW1f = (const float*)d_in[10];
    const float* eU1f = (const float*)d_in[11];
    const float* eb1f = (const float*)d_in[12];
    const float* eW1b = (const float*)d_in[13];
    const float* eU1b = (const float*)d_in[14];
    const float* eb1b = (const float*)d_in[15];
    const float* out_W = (const float*)d_in[16];
    const float* out_b = (const float*)d_in[17];
    const float* hpW  = (const float*)d_in[18];
    const float* hpb  = (const float*)d_in[19];
    const float* cpW  = (const float*)d_in[20];
    const float* cpb  = (const float*)d_in[21];
    const float* dW0  = (const float*)d_in[22];
    const float* dU0  = (const float*)d_in[23];
    const float* db0  = (const float*)d_in[24];
    const float* dW1  = (const float*)d_in[25];
    const float* dU1  = (const float*)d_in[26];
    const float* db1  = (const float*)d_in[27];
    const float* fcW  = (const float*)d_in[28];
    const float* fcb  = (const float*)d_in[29];
    float* out = (float*)d_out;

    float* xsrc = sym(d_xsrc);
    float* ytrg = sym(d_ytrg);
    float* xpf  = sym(d_xpf);
    float* xpb  = sym(d_xpb);
    float* x1   = sym(d_x1);
    float* x2   = sym(d_x2);
    float* enc  = sym(d_enc);
    float* y1   = sym(d_y1);
    float* y2   = sym(d_y2);
    float* comb = sym(d_comb);
    float* ecT0 = sym(d_ecT0);
    float* ecT1 = sym(d_ecT1);
    float* ehT0 = sym(d_ehT0);
    float* ehT1 = sym(d_ehT1);
    float* dh0  = sym(d_dh0);
    float* dh1  = sym(d_dh1);
    float* dc0  = sym(d_dc0);
    float* dc1  = sym(d_dc1);

    static bool attr_done = false;
    if (!attr_done) {
        cudaFuncSetAttribute(gemm_tf32, cudaFuncAttributeMaxDynamicSharedMemorySize, GEMM_SMEM);
        cudaFuncSetAttribute(lstm_scan_enc, cudaFuncAttributeMaxDynamicSharedMemorySize, SCAN_SMEM);
        cudaFuncSetAttribute(lstm_scan_dec, cudaFuncAttributeMaxDynamicSharedMemorySize, SCAN_SMEM);
        attr_done = true;
    }

    embed_kernel<<<(BB*SS*EE + 255)/256, 256>>>(xsrc, src_emb, src_seq, BB*SS*EE);
    embed_kernel<<<(BB*TN*EE + 255)/256, 256>>>(ytrg, trg_emb, trg_seq, BB*TN*EE);

    const dim3 gXP((BB*SS)/128, H4/128);     // (24, 16) M-fast
    const dim3 gENC((BB*SS)/128, HH/128);    // (24, 4)
    const dim3 gPROJ(HH/128, 1);             // fp32 kernel layout (N-x, M-y)
    const dim3 gFC((BB*TN)/128, VV/128);     // (24, 250)

    // ===== encoder layer 0 =====
    gemm_tf32<<<gXP, 256, GEMM_SMEM>>>(xsrc, eW0f, eb0f, xpf, BB*SS, H4, EE);
    gemm_tf32<<<gXP, 256, GEMM_SMEM>>>(xsrc, eW0b, eb0b, xpb, BB*SS, H4, EE);
    flag_reset_kernel<<<1, 128>>>();
    lstm_scan_enc<<<128, 256, SCAN_SMEM>>>(xpf, xpb, eU0f, eU0b, x1, ecT0);

    // ===== encoder layer 1 =====
    gemm_tf32<<<gXP, 256, GEMM_SMEM>>>(x1, eW1f, eb1f, xpf, BB*SS, H4, H2);
    gemm_tf32<<<gXP, 256, GEMM_SMEM>>>(x1, eW1b, eb1b, xpb, BB*SS, H4, H2);
    flag_reset_kernel<<<1, 128>>>();
    lstm_scan_enc<<<128, 256, SCAN_SMEM>>>(xpf, xpb, eU1f, eU1b, x2, ecT1);

    gemm_tf32<<<gENC, 256, GEMM_SMEM>>>(x2, out_W, out_b, enc, BB*SS, HH, H2);

    gather_hT<<<(2*BB*H2 + 255)/256, 256>>>(2*BB*H2);
    sgemm_bias_nt<<<gPROJ, 256>>>(ehT0, hpW,           hpb,       dh0, BB, HH, H2);
    sgemm_bias_nt<<<gPROJ, 256>>>(ehT1, hpW + HH*H2,   hpb + HH,  dh1, BB, HH, H2);
    sgemm_bias_nt<<<gPROJ, 256>>>(ecT0, cpW,           cpb,       dc0, BB, HH, H2);
    sgemm_bias_nt<<<gPROJ, 256>>>(ecT1, cpW + HH*H2,   cpb + HH,  dc1, BB, HH, H2);

    // ===== decoder layer 0 =====
    gemm_tf32<<<gXP, 256, GEMM_SMEM>>>(ytrg, dW0, db0, xpf, BB*TN, H4, EE);
    flag_reset_kernel<<<1, 128>>>();
    lstm_scan_dec<<<64, 256, SCAN_SMEM>>>(xpf, dU0, dh0, dc0, y1);

    // ===== decoder layer 1 =====
    gemm_tf32<<<gXP, 256, GEMM_SMEM>>>(y1, dW1, db1, xpf, BB*TN, H4, HH);
    flag_reset_kernel<<<1, 128>>>();
    lstm_scan_dec<<<64, 256, SCAN_SMEM>>>(xpf, dU1, dh1, dc1, y2);

    // ===== attention + concat =====
    attn_kernel<<<BB*TN, 128>>>(y2, enc, src_seq, comb);

    // ===== final FC on tensor cores (TF32) =====
    gemm_tf32<<<gFC, 256, GEMM_SMEM>>>(comb, fcW, fcb, out, BB*TN, VV, H2);
}

// round 11
// speedup vs baseline: 1.7149x; 1.2432x over previous
#include <cuda_runtime.h>
#include <math.h>
#include <mma.h>
using namespace nvcuda;

#define BB 32
#define SS 96
#define TN 96
#define EE 256
#define HH 512
#define H4 2048
#define H2 1024
#define VV 32000

// ---------------- static scratch (no allocations) ----------------
__device__ float d_xsrc[BB*SS*EE];
__device__ float d_ytrg[BB*TN*EE];
__device__ float d_xpf[BB*SS*H4];
__device__ float d_xpb[BB*SS*H4];
__device__ float d_x1[BB*SS*H2];
__device__ float d_x2[BB*SS*H2];
__device__ float d_enc[BB*SS*HH];
__device__ float d_y1[BB*TN*HH];
__device__ float d_y2[BB*TN*HH];
__device__ float d_comb[BB*TN*H2];
__device__ float d_ecT0[BB*H2];
__device__ float d_ecT1[BB*H2];
__device__ float d_ehT0[BB*H2];
__device__ float d_ehT1[BB*H2];
__device__ float d_dh0[BB*HH];
__device__ float d_dh1[BB*HH];
__device__ float d_dc0[BB*HH];
__device__ float d_dc1[BB*HH];

// per-block step flags (distributed barrier); [dir*64 + jblk]
__device__ unsigned d_flag[128];

__global__ void flag_reset_kernel() {
    if (threadIdx.x < 128) d_flag[threadIdx.x] = 0u;
}

// ---------------- helpers ----------------
__global__ void embed_kernel(float* __restrict__ out, const float* __restrict__ emb,
                             const int* __restrict__ seq, int n) {
    int i = blockIdx.x * blockDim.x + threadIdx.x;
    if (i < n) {
        int tok = seq[i >> 8];
        out[i] = emb[(size_t)tok * EE + (i & 255)];
    }
}

// ---------------- fused 4x small projection (M=32, N=512, K=1024) ----------------
__global__ __launch_bounds__(256) void proj4_kernel(
    const float* __restrict__ A0, const float* __restrict__ A1,
    const float* __restrict__ A2, const float* __restrict__ A3,
    const float* __restrict__ hpW, const float* __restrict__ hpb,
    const float* __restrict__ cpW, const float* __restrict__ cpb,
    float* __restrict__ C0, float* __restrict__ C1,
    float* __restrict__ C2, float* __restrict__ C3)
{
    const float* A; const float* W; const float* bias; float* C;
    switch (blockIdx.z) {
        case 0: A = A0; W = hpW;            bias = hpb;      C = C0; break;
        case 1: A = A1; W = hpW + HH*H2;    bias = hpb + HH; C = C1; break;
        case 2: A = A2; W = cpW;            bias = cpb;      C = C2; break;
        default:A = A3; W = cpW + HH*H2;    bias = cpb + HH; C = C3; break;
    }
    const int M = BB, N = HH, K = H2;

    __shared__ float As[16][132];
    __shared__ float Ws[16][132];
    const int bn = blockIdx.x * 128;
    const int tid = threadIdx.x;
    const int trow = (tid >> 4) * 8;
    const int tcol = (tid & 15) * 8;

    float acc[8][8];
#pragma unroll
    for (int i = 0; i < 8; i++)
#pragma unroll
        for (int j = 0; j < 8; j++) acc[i][j] = 0.f;

    for (int k0 = 0; k0 < K; k0 += 16) {
#pragma unroll
        for (int i = 0; i < 2; i++) {
            int q = tid + i * 256;
            int r = q >> 2;
            int c = (q & 3) * 4;
            float4 v = make_float4(0.f, 0.f, 0.f, 0.f);
            if (r < M) v = *(const float4*)(A + (size_t)r * K + k0 + c);
            As[c + 0][r] = v.x; As[c + 1][r] = v.y; As[c + 2][r] = v.z; As[c + 3][r] = v.w;
            float4 u = *(const float4*)(W + (size_t)(bn + r) * K + k0 + c);
            Ws[c + 0][r] = u.x; Ws[c + 1][r] = u.y; Ws[c + 2][r] = u.z; Ws[c + 3][r] = u.w;
        }
        __syncthreads();
#pragma unroll
        for (int kk = 0; kk < 16; kk++) {
            float4 a0 = *(const float4*)&As[kk][trow];
            float4 a1 = *(const float4*)&As[kk][trow + 4];
            float4 b0 = *(const float4*)&Ws[kk][tcol];
            float4 b1 = *(const float4*)&Ws[kk][tcol + 4];
            float av[8] = {a0.x, a0.y, a0.z, a0.w, a1.x, a1.y, a1.z, a1.w};
            float bv[8] = {b0.x, b0.y, b0.z, b0.w, b1.x, b1.y, b1.z, b1.w};
#pragma unroll
            for (int i = 0; i < 8; i++)
#pragma unroll
                for (int j = 0; j < 8; j++) acc[i][j] += av[i] * bv[j];
        }
        __syncthreads();
    }

    float bb[8];
#pragma unroll
    for (int j = 0; j < 8; j++) bb[j] = bias[bn + tcol + j];
#pragma unroll
    for (int i = 0; i < 8; i++) {
        int r = trow + i;
        if (r < M) {
            float* cp = C + (size_t)r * N + bn + tcol;
#pragma unroll
            for (int j = 0; j < 8; j += 4) {
                float4 v;
                v.x = acc[i][j + 0] + bb[j + 0];
                v.y = acc[i][j + 1] + bb[j + 1];
                v.z = acc[i][j + 2] + bb[j + 2];
                v.w = acc[i][j + 3] + bb[j + 3];
                *(float4*)(cp + j) = v;
            }
        }
    }
}

// ---------------- TF32 tensor-core GEMM (FC + big projections) ----------------
__global__ __launch_bounds__(256) void gemm_tf32(
    const float* __restrict__ A, const float* __restrict__ W,
    const float* __restrict__ bias, float* __restrict__ C,
    int M, int N, int K)
{
    extern __shared__ float sm[];
    float* Ab[2] = { sm,          sm + 5120 };
    float* Bb[2] = { sm + 10240,  sm + 15360 };

    const int bm = blockIdx.x * 128;
    const int bn = blockIdx.y * 128;
    const int tid  = threadIdx.x;
    const int warp = tid >> 5;
    const int lane = tid & 31;
    const int wm = warp & 3;
    const int wn = warp >> 2;

    wmma::fragment<wmma::accumulator, 16, 16, 8, float> c[2][4];
#pragma unroll
    for (int i = 0; i < 2; i++)
#pragma unroll
        for (int j = 0; j < 4; j++) wmma::fill_fragment(c[i][j], 0.f);

    const int lr = tid >> 1;
    const int lc = (tid & 1) * 16;
    const float* ap = A + (size_t)(bm + lr) * K + lc;
    const float* wp = W + (size_t)(bn + lr) * K + lc;

    float4 ra[4], rw[4];
#pragma unroll
    for (int q = 0; q < 4; q++) {
        ra[q] = *(const float4*)(ap + q * 4);
        rw[q] = *(const float4*)(wp + q * 4);
    }
    {
        float* ad = Ab[0] + lr * 40 + lc;
        float* bd = Bb[0] + lr * 40 + lc;
#pragma unroll
        for (int q = 0; q < 4; q++) {
            ad[q*4+0] = wmma::__float_to_tf32(ra[q].x);
            ad[q*4+1] = wmma::__float_to_tf32(ra[q].y);
            ad[q*4+2] = wmma::__float_to_tf32(ra[q].z);
            ad[q*4+3] = wmma::__float_to_tf32(ra[q].w);
            bd[q*4+0] = wmma::__float_to_tf32(rw[q].x);
            bd[q*4+1] = wmma::__float_to_tf32(rw[q].y);
            bd[q*4+2] = wmma::__float_to_tf32(rw[q].z);
            bd[q*4+3] = wmma::__float_to_tf32(rw[q].w);
        }
    }
    __syncthreads();

    const int ksteps = K >> 5;
    int cur = 0;
    for (int ks = 0; ks < ksteps; ks++) {
        const bool more = (ks + 1 < ksteps);
        if (more) {
            const float* a2 = ap + (ks + 1) * 32;
            const float* w2 = wp + (ks + 1) * 32;
#pragma unroll
            for (int q = 0; q < 4; q++) {
                ra[q] = *(const float4*)(a2 + q * 4);
                rw[q] = *(const float4*)(w2 + q * 4);
            }
        }
        const float* As = Ab[cur];
        const float* Bs = Bb[cur];
#pragma unroll
        for (int kk = 0; kk < 4; kk++) {
            wmma::fragment<wmma::matrix_a, 16, 16, 8, wmma::precision::tf32, wmma::row_major> a[2];
            wmma::fragment<wmma::matrix_b, 16, 16, 8, wmma::precision::tf32, wmma::col_major> b[4];
#pragma unroll
            for (int i = 0; i < 2; i++)
                wmma::load_matrix_sync(a[i], As + (wm * 32 + i * 16) * 40 + kk * 8, 40);
#pragma unroll
            for (int j = 0; j < 4; j++)
                wmma::load_matrix_sync(b[j], Bs + (wn * 64 + j * 16) * 40 + kk * 8, 40);
#pragma unroll
            for (int i = 0; i < 2; i++)
#pragma unroll
                for (int j = 0; j < 4; j++)
                    wmma::mma_sync(c[i][j], a[i], b[j], c[i][j]);
        }
        if (more) {
            float* ad = Ab[cur ^ 1] + lr * 40 + lc;
            float* bd = Bb[cur ^ 1] + lr * 40 + lc;
#pragma unroll
            for (int q = 0; q < 4; q++) {
                ad[q*4+0] = wmma::__float_to_tf32(ra[q].x);
                ad[q*4+1] = wmma::__float_to_tf32(ra[q].y);
                ad[q*4+2] = wmma::__float_to_tf32(ra[q].z);
                ad[q*4+3] = wmma::__float_to_tf32(ra[q].w);
                bd[q*4+0] = wmma::__float_to_tf32(rw[q].x);
                bd[q*4+1] = wmma::__float_to_tf32(rw[q].y);
                bd[q*4+2] = wmma::__float_to_tf32(rw[q].z);
                bd[q*4+3] = wmma::__float_to_tf32(rw[q].w);
            }
            __syncthreads();
            cur ^= 1;
        }
    }
    __syncthreads();

    float* wbuf = sm + warp * 320;
    const int er = lane >> 1;
    const int ec = (lane & 1) * 8;
#pragma unroll
    for (int i = 0; i < 2; i++) {
#pragma unroll
        for (int j = 0; j < 4; j++) {
            wmma::store_matrix_sync(wbuf, c[i][j], 20, wmma::mem_row_major);
            __syncwarp();
            const int gr = bm + wm * 32 + i * 16 + er;
            const int gc = bn + wn * 64 + j * 16 + ec;
            const float* bp = bias + gc;
            float* dst = C + (size_t)gr * N + gc;
            float4 v0, v1;
            v0.x = wbuf[er * 20 + ec + 0] + bp[0];
            v0.y = wbuf[er * 20 + ec + 1] + bp[1];
            v0.z = wbuf[er * 20 + ec + 2] + bp[2];
            v0.w = wbuf[er * 20 + ec + 3] + bp[3];
            v1.x = wbuf[er * 20 + ec + 4] + bp[4];
            v1.y = wbuf[er * 20 + ec + 5] + bp[5];
            v1.z = wbuf[er * 20 + ec + 6] + bp[6];
            v1.w = wbuf[er * 20 + ec + 7] + bp[7];
            *(float4*)(dst)     = v0;
            *(float4*)(dst + 4) = v1;
            __syncwarp();
        }
    }
}

// ---------------- persistent LSTM scan: tensor-core gemv ----------------
// Per block (256 thr, 8 warps): D[32 batch x 32 gaterow] = h[32x512] @ Uslice^T.
// U_hi fragments preloaded in registers (warp w owns k-slices 8w..8w+7).
// h staged hi/lo each step: D = A_hi*B_hi + A_lo*B_hi  (exact h x tf32 U).
// 8-warp k-partials reduced through smem (ld=36: wmma requires ld % 4 == 0).
#define HPAD 520
#define RPAD 36
#define RWARP (32*RPAD)
#define SCAN_SMEM ((2*32*HPAD + 8*RWARP) * 4)

__device__ __forceinline__ void scan_mma(
    const float* __restrict__ xp,   // [B][96][2048] for this dir
    const float* __restrict__ U,    // [2048][512]
    const float* __restrict__ h0,   // [B][512] initial h (null => zeros)
    const float* __restrict__ c0,   // [B][512] initial c (null => zeros)
    float* __restrict__ hs,         // out: (b*96+t)*ostr + j (dir offset pre-added)
    float* __restrict__ cT,         // final c out (stride H2), may be null
    unsigned* __restrict__ flags,   // 64 flags for this group
    int myblk,
    int ostr, int rev, int j0, float* sm)
{
    float* Hhi = sm;                 // [32][HPAD]
    float* Hlo = sm + 32*HPAD;       // [32][HPAD]
    float* RED = sm + 64*HPAD;       // [8 warps][32*RPAD]
    const int tid  = threadIdx.x;
    const int warp = tid >> 5;

    // ---- stage tf32-rounded U slice into Hhi, preload B fragments ----
    {
        const int r = tid >> 3;                       // gate-row 0..31
        const int gr = (r >> 3) * HH + j0 + (r & 7);  // gate*512 + j0 + unit
        const float* urow = U + (size_t)gr * HH;
#pragma unroll
        for (int q = 0; q < 4; q++) {
            int k = (tid & 7) * 16 + q * 128;
#pragma unroll
            for (int p = 0; p < 4; p++) {
                float4 v = *(const float4*)(urow + k + p * 4);
                float* d = Hhi + r * HPAD + k + p * 4;
                d[0] = wmma::__float_to_tf32(v.x);
                d[1] = wmma::__float_to_tf32(v.y);
                d[2] = wmma::__float_to_tf32(v.z);
                d[3] = wmma::__float_to_tf32(v.w);
            }
        }
    }
    __syncthreads();
    wmma::fragment<wmma::matrix_b, 16, 16, 8, wmma::precision::tf32, wmma::col_major> bfr[8][2];
#pragma unroll
    for (int s = 0; s < 8; s++)
#pragma unroll
        for (int nt = 0; nt < 2; nt++)
            wmma::load_matrix_sync(bfr[s][nt], Hhi + nt * 16 * HPAD + (warp * 8 + s) * 8, HPAD);
    __syncthreads();

    const int pu = tid >> 5;           // unit 0..7
    const int pb = tid & 31;           // batch 0..31
    float creg = c0 ? c0[(size_t)pb * HH + j0 + pu] : 0.f;
    volatile unsigned* myflag = (tid < 64) ? (flags + tid) : nullptr;

    for (int t = 0; t < TN; t++) {
        const int tt = rev ? (TN - 1 - t) : t;
        const size_t xb = ((size_t)pb * TN + tt) * H4 + j0 + pu;
        const float xgi = xp[xb];
        const float xgf = xp[xb + 512];
        const float xgg = xp[xb + 1024];
        const float xgo = xp[xb + 1536];

        const float* hb = nullptr;
        size_t hstr = 0;
        if (t == 0) {
            if (h0) { hb = h0; hstr = HH; }
        } else {
            const int tprev = rev ? (tt + 1) : (tt - 1);
            hb = hs + (size_t)tprev * ostr;
            hstr = (size_t)TN * ostr;
        }

        if (hb) {
            if (t > 0) {
                if (myflag) { while (*myflag < (unsigned)t) { } }
                __syncthreads();
            }
            // stage h hi/lo
            {
                const int r = tid >> 3;                   // batch row
                const float* hrow = hb + (size_t)r * hstr;
#pragma unroll
                for (int q = 0; q < 4; q++) {
                    int k = (tid & 7) * 16 + q * 128;
#pragma unroll
                    for (int p = 0; p < 4; p++) {
                        float4 v = __ldcg((const float4*)(hrow + k + p * 4));
                        float* dh = Hhi + r * HPAD + k + p * 4;
                        float* dl = Hlo + r * HPAD + k + p * 4;
                        float hx = wmma::__float_to_tf32(v.x);
                        float hy = wmma::__float_to_tf32(v.y);
                        float hz = wmma::__float_to_tf32(v.z);
                        float hw = wmma::__float_to_tf32(v.w);
                        dh[0] = hx; dl[0] = v.x - hx;
                        dh[1] = hy; dl[1] = v.y - hy;
                        dh[2] = hz; dl[2] = v.z - hz;
                        dh[3] = hw; dl[3] = v.w - hw;
                    }
                }
            }
            __syncthreads();

            wmma::fragment<wmma::accumulator, 16, 16, 8, float> acc[2][2];
#pragma unroll
            for (int mt = 0; mt < 2; mt++)
#pragma unroll
                for (int nt = 0; nt < 2; nt++) wmma::fill_fragment(acc[mt][nt], 0.f);

#pragma unroll
            for (int s = 0; s < 8; s++) {
                const int ko = (warp * 8 + s) * 8;
#pragma unroll
                for (int mt = 0; mt < 2; mt++) {
                    wmma::fragment<wmma::matrix_a, 16, 16, 8, wmma::precision::tf32, wmma::row_major> ah, al;
                    wmma::load_matrix_sync(ah, Hhi + mt * 16 * HPAD + ko, HPAD);
                    wmma::load_matrix_sync(al, Hlo + mt * 16 * HPAD + ko, HPAD);
#pragma unroll
                    for (int nt = 0; nt < 2; nt++) {
                        wmma::mma_sync(acc[mt][nt], ah, bfr[s][nt], acc[mt][nt]);
                        wmma::mma_sync(acc[mt][nt], al, bfr[s][nt], acc[mt][nt]);
                    }
                }
            }
#pragma unroll
            for (int mt = 0; mt < 2; mt++)
#pragma unroll
                for (int nt = 0; nt < 2; nt++)
                    wmma::store_matrix_sync(RED + warp * RWARP + (mt * 16) * RPAD + nt * 16,
                                            acc[mt][nt], RPAD, wmma::mem_row_major);
            __syncthreads();
        }

        float s0 = 0.f, s1 = 0.f, s2 = 0.f, s3 = 0.f;
        if (hb) {
#pragma unroll
            for (int w = 0; w < 8; w++) {
                const float* rp = RED + w * RWARP + pb * RPAD + pu;
                s0 += rp[0]; s1 += rp[8]; s2 += rp[16]; s3 += rp[24];
            }
        }
        {
            float gi = s0 + xgi;
            float gf = s1 + xgf;
            float gg = s2 + xgg;
            float go = s3 + xgo;
            float si = 1.f / (1.f + expf(-gi));
            float sf = 1.f / (1.f + expf(-gf));
            float so = 1.f / (1.f + expf(-go));
            float tg = tanhf(gg);
            creg = sf * creg + si * tg;
            __stcg(hs + ((size_t)pb * TN + tt) * ostr + j0 + pu, so * tanhf(creg));
        }
        __syncthreads();
        if (tid == 0) {
            __threadfence();
            atomicExch(&flags[myblk], (unsigned)(t + 1));
        }
    }

    if (cT) cT[(size_t)pb * H2 + j0 + pu] = creg;
}

__global__ __launch_bounds__(256) void lstm_scan_enc(
    const float* __restrict__ xpf, const float* __restrict__ xpb,
    const float* __restrict__ Uf,  const float* __restrict__ Ub,
    float* __restrict__ hs, float* __restrict__ cT)
{
    extern __shared__ float sm[];
    const int dir = blockIdx.x >> 6;
    const int jb  = blockIdx.x & 63;
    scan_mma(dir ? xpb : xpf, dir ? Ub : Uf, nullptr, nullptr,
             hs + dir * 512, cT + dir * 512,
             d_flag + dir * 64, jb, H2, dir, jb * 8, sm);
}

__global__ __launch_bounds__(256) void lstm_scan_dec(
    const float* __restrict__ xp, const float* __restrict__ U,
    const float* __restrict__ h0, const float* __restrict__ c0,
    float* __restrict__ hs)
{
    extern __shared__ float sm[];
    const int jb = blockIdx.x;
    scan_mma(xp, U, h0, c0, hs, nullptr, d_flag, jb, HH, 0, jb * 8, sm);
}

__global__ void gather_hT(int n) {
    int i = blockIdx.x * blockDim.x + threadIdx.x;
    if (i >= n) return;
    int l = i >> 15;
    int r = i & 32767;
    int b = r >> 10;
    int j = r & 1023;
    const float* src = l ? d_x2 : d_x1;
    int tt = (j < 512) ? (SS - 1) : 0;
    float v = src[((size_t)b * SS + tt) * H2 + j];
    (l ? d_ehT1 : d_ehT0)[b * H2 + j] = v;
}

// ---------------- attention + concat ----------------
__global__ __launch_bounds__(128) void attn_kernel(
    const float* __restrict__ y, const float* __restrict__ enc,
    const int* __restrict__ src_seq, float* __restrict__ comb)
{
    const int bt = blockIdx.x;
    const int b = bt / TN;
    __shared__ float ysm[HH];
    __shared__ float esm[SS];
    __shared__ float red[1];
    const int tid = threadIdx.x;
    const float* yrow = y + (size_t)bt * HH;
#pragma unroll
    for (int i = 0; i < 4; i++) ysm[tid + i * 128] = yrow[tid + i * 128];
    __syncthreads();

    const int lane = tid & 31, w = tid >> 5;
    for (int s = w; s < SS; s += 4) {
        const float* er = enc + ((size_t)b * SS + s) * HH;
        float p = 0.f;
        for (int d = lane; d < HH; d += 32) p += ysm[d] * er[d];
#pragma unroll
        for (int off = 16; off; off >>= 1) p += __shfl_xor_sync(0xffffffffu, p, off);
        if (lane == 0) esm[s] = (src_seq[b * SS + s] != 0) ? p : -1e10f;
    }
    __syncthreads();

    if (w == 0) {
        float m = -1e30f;
        for (int s = lane; s < SS; s += 32) m = fmaxf(m, esm[s]);
#pragma unroll
        for (int off = 16; off; off >>= 1) m = fmaxf(m, __shfl_xor_sync(0xffffffffu, m, off));
        float sum = 0.f;
        for (int s = lane; s < SS; s += 32) { float e = expf(esm[s] - m); esm[s] = e; sum += e; }
#pragma unroll
        for (int off = 16; off; off >>= 1) sum += __shfl_xor_sync(0xffffffffu, sum, off);
        if (lane == 0) red[0] = 1.f / sum;
    }
    __syncthreads();

    const float inv = red[0];
    const int d = tid * 4;
    float4 ctx = make_float4(0.f, 0.f, 0.f, 0.f);
    for (int s = 0; s < SS; s++) {
        float a = esm[s] * inv;
        float4 ev = *(const float4*)(enc + ((size_t)b * SS + s) * HH + d);
        ctx.x += a * ev.x; ctx.y += a * ev.y; ctx.z += a * ev.z; ctx.w += a * ev.w;
    }
    float* crow = comb + (size_t)bt * H2;
#pragma unroll
    for (int i = 0; i < 4; i++) crow[tid + i * 128] = ysm[tid + i * 128];
    *(float4*)(crow + HH + d) = ctx;
}

// ---------------- host launcher ----------------
static float* sym(const void* s) {
    void* p = nullptr;
    cudaGetSymbolAddress(&p, s);
    return (float*)p;
}

#define GEMM_SMEM (4 * 5120 * 4)

extern "C" void kernel_launch(void* const* d_in, const int* in_sizes, int n_in,
                              void* d_out, int out_size) {
    const int*   src_seq = (const int*)d_in[0];
    const int*   trg_seq = (const int*)d_in[1];
    const float* src_emb = (const float*)d_in[2];
    const float* trg_emb = (const float*)d_in[3];
    const float* eW0f = (const float*)d_in[4];
    const float* eU0f = (const float*)d_in[5];
    const float* eb0f = (const float*)d_in[6];
    const float* eW0b = (const float*)d_in[7];
    const float* eU0b = (const float*)d_in[8];
    const float* eb0b = (const float*)d_in[9];
    const float* eW1f = (const float*)d_in[10];
    const float* eU1f = (const float*)d_in[11];
    const float* eb1f = (const float*)d_in[12];
    const float* eW1b = (const float*)d_in[13];
    const float* eU1b = (const float*)d_in[14];
    const float* eb1b = (const float*)d_in[15];
    const float* out_W = (const float*)d_in[16];
    const float* out_b = (const float*)d_in[17];
    const float* hpW  = (const float*)d_in[18];
    const float* hpb  = (const float*)d_in[19];
    const float* cpW  = (const float*)d_in[20];
    const float* cpb  = (const float*)d_in[21];
    const float* dW0  = (const float*)d_in[22];
    const float* dU0  = (const float*)d_in[23];
    const float* db0  = (const float*)d_in[24];
    const float* dW1  = (const float*)d_in[25];
    const float* dU1  = (const float*)d_in[26];
    const float* db1  = (const float*)d_in[27];
    const float* fcW  = (const float*)d_in[28];
    const float* fcb  = (const float*)d_in[29];
    float* out = (float*)d_out;

    float* xsrc = sym(d_xsrc);
    float* ytrg = sym(d_ytrg);
    float* xpf  = sym(d_xpf);
    float* xpb  = sym(d_xpb);
    float* x1   = sym(d_x1);
    float* x2   = sym(d_x2);
    float* enc  = sym(d_enc);
    float* y1   = sym(d_y1);
    float* y2   = sym(d_y2);
    float* comb = sym(d_comb);
    float* ecT0 = sym(d_ecT0);
    float* ecT1 = sym(d_ecT1);
    float* ehT0 = sym(d_ehT0);
    float* ehT1 = sym(d_ehT1);
    float* dh0  = sym(d_dh0);
    float* dh1  = sym(d_dh1);
    float* dc0  = sym(d_dc0);
    float* dc1  = sym(d_dc1);

    static bool attr_done = false;
    if (!attr_done) {
        cudaFuncSetAttribute(gemm_tf32, cudaFuncAttributeMaxDynamicSharedMemorySize, GEMM_SMEM);
        cudaFuncSetAttribute(lstm_scan_enc, cudaFuncAttributeMaxDynamicSharedMemorySize, SCAN_SMEM);
        cudaFuncSetAttribute(lstm_scan_dec, cudaFuncAttributeMaxDynamicSharedMemorySize, SCAN_SMEM);
        attr_done = true;
    }

    embed_kernel<<<(BB*SS*EE + 255)/256, 256>>>(xsrc, src_emb, src_seq, BB*SS*EE);
    embed_kernel<<<(BB*TN*EE + 255)/256, 256>>>(ytrg, trg_emb, trg_seq, BB*TN*EE);

    const dim3 gXP((BB*SS)/128, H4/128);     // (24, 16) M-fast
    const dim3 gENC((BB*SS)/128, HH/128);    // (24, 4)
    const dim3 gP4(HH/128, 1, 4);            // fused 4 projections
    const dim3 gFC((BB*TN)/128, VV/128);     // (24, 250)

    // ===== encoder layer 0 =====
    gemm_tf32<<<gXP, 256, GEMM_SMEM>>>(xsrc, eW0f, eb0f, xpf, BB*SS, H4, EE);
    gemm_tf32<<<gXP, 256, GEMM_SMEM>>>(xsrc, eW0b, eb0b, xpb, BB*SS, H4, EE);
    flag_reset_kernel<<<1, 128>>>();
    lstm_scan_enc<<<128, 256, SCAN_SMEM>>>(xpf, xpb, eU0f, eU0b, x1, ecT0);

    // ===== encoder layer 1 =====
    gemm_tf32<<<gXP, 256, GEMM_SMEM>>>(x1, eW1f, eb1f, xpf, BB*SS, H4, H2);
    gemm_tf32<<<gXP, 256, GEMM_SMEM>>>(x1, eW1b, eb1b, xpb, BB*SS, H4, H2);
    flag_reset_kernel<<<1, 128>>>();
    lstm_scan_enc<<<128, 256, SCAN_SMEM>>>(xpf, xpb, eU1f, eU1b, x2, ecT1);

    gemm_tf32<<<gENC, 256, GEMM_SMEM>>>(x2, out_W, out_b, enc, BB*SS, HH, H2);

    gather_hT<<<(2*BB*H2 + 255)/256, 256>>>(2*BB*H2);
    proj4_kernel<<<gP4, 256>>>(ehT0, ehT1, ecT0, ecT1, hpW, hpb, cpW, cpb,
                               dh0, dh1, dc0, dc1);

    // ===== decoder layer 0 =====
    gemm_tf32<<<gXP, 256, GEMM_SMEM>>>(ytrg, dW0, db0, xpf, BB*TN, H4, EE);
    flag_reset_kernel<<<1, 128>>>();
    lstm_scan_dec<<<64, 256, SCAN_SMEM>>>(xpf, dU0, dh0, dc0, y1);

    // ===== decoder layer 1 =====
    gemm_tf32<<<gXP, 256, GEMM_SMEM>>>(y1, dW1, db1, xpf, BB*TN, H4, HH);
    flag_reset_kernel<<<1, 128>>>();
    lstm_scan_dec<<<64, 256, SCAN_SMEM>>>(xpf, dU1, dh1, dc1, y2);

    // ===== attention + concat =====
    attn_kernel<<<BB*TN, 128>>>(y2, enc, src_seq, comb);

    // ===== final FC on tensor cores (TF32) =====
    gemm_tf32<<<gFC, 256, GEMM_SMEM>>>(comb, fcW, fcb, out, BB*TN, VV, H2);
}